// round 8
// baseline (speedup 1.0000x reference)
#include <cuda_runtime.h>
#include <cuda_bf16.h>
#include <math.h>
#include <stdint.h>

#define BB 4
#define NN 8192
#define CC 256
#define HH 8
#define DD 64
#define HD 512
#define NCHUNK 16
#define CHK (NN / NCHUNK)   // 512

typedef unsigned long long u64t;

// ---------------------------------------------------------------------------
// Scratch (__device__ globals; allocation-free rule)
// ---------------------------------------------------------------------------
__device__ float g_q[BB * HH * NN * DD];            // [bh][n][d] fp32
__device__ float g_k[BB * HH * NN * DD];
__device__ float g_v[BB * HH * NN * DD];
__device__ float g_part[NCHUNK * BB * HH * DD * DD];
__device__ float g_dots[BB * HH * DD * DD];
__device__ float g_trig[NN * 64];                   // per n: cx[16] sx[16] cy[16] sy[16]

__device__ __nv_bfloat16 g_xh[32768 * 256];         // X split
__device__ __nv_bfloat16 g_xl[32768 * 256];
__device__ __nv_bfloat16 g_wh[1536 * 256];          // [Wq;Wk;Wv] split
__device__ __nv_bfloat16 g_wl[1536 * 256];
__device__ __nv_bfloat16 g_woh[256 * 512];          // Wo split
__device__ __nv_bfloat16 g_wol[256 * 512];
__device__ __nv_bfloat16 g_uh[32768 * 512];         // u split, [m][h*64+d]
__device__ __nv_bfloat16 g_ul[32768 * 512];

// ---------------------------------------------------------------------------
// helpers
// ---------------------------------------------------------------------------
__device__ __forceinline__ uint32_t smem_u32(const void* p) {
    uint32_t a;
    asm("{ .reg .u64 t; cvta.to.shared.u64 t, %1; cvt.u32.u64 %0, t; }" : "=r"(a) : "l"(p));
    return a;
}
__device__ __forceinline__ void ldm_x4(uint32_t& r0, uint32_t& r1, uint32_t& r2, uint32_t& r3,
                                       uint32_t addr) {
    asm volatile("ldmatrix.sync.aligned.m8n8.x4.shared.b16 {%0,%1,%2,%3}, [%4];"
                 : "=r"(r0), "=r"(r1), "=r"(r2), "=r"(r3) : "r"(addr));
}
__device__ __forceinline__ void mma_bf16(float* d, const uint32_t* a, const uint32_t* b) {
    asm volatile(
        "mma.sync.aligned.m16n8k16.row.col.f32.bf16.bf16.f32 "
        "{%0,%1,%2,%3}, {%4,%5,%6,%7}, {%8,%9}, {%0,%1,%2,%3};"
        : "+f"(d[0]), "+f"(d[1]), "+f"(d[2]), "+f"(d[3])
        : "r"(a[0]), "r"(a[1]), "r"(a[2]), "r"(a[3]), "r"(b[0]), "r"(b[1]));
}

// ---- packed f32x2 helpers (SIMT kernels) ----------------------------------
__device__ __forceinline__ u64t ffma2(u64t a, u64t b, u64t c) {
    u64t d;
    asm("fma.rn.f32x2 %0, %1, %2, %3;" : "=l"(d) : "l"(a), "l"(b), "l"(c));
    return d;
}
__device__ __forceinline__ u64t pack2(float x) {
    u64t d;
    asm("mov.b64 %0, {%1, %1};" : "=l"(d) : "r"(__float_as_uint(x)));
    return d;
}
__device__ __forceinline__ void unpack2(u64t v, float& lo, float& hi) {
    unsigned a, b;
    asm("mov.b64 {%0, %1}, %2;" : "=r"(a), "=r"(b) : "l"(v));
    lo = __uint_as_float(a);
    hi = __uint_as_float(b);
}
__device__ __forceinline__ void bf16split(float x, __nv_bfloat16& h, __nv_bfloat16& l) {
    h = __float2bfloat16_rn(x);
    l = __float2bfloat16_rn(x - __bfloat162float(h));
}

// ---------------------------------------------------------------------------
// trig table
// ---------------------------------------------------------------------------
__global__ __launch_bounds__(256) void trig_init(const float* __restrict__ pos)
{
    const int idx = blockIdx.x * 256 + threadIdx.x;
    const int n = idx >> 4;
    const int j = idx & 15;
    const float invf = exp2f(-(float)j * (13.2877123795494f / 16.0f));
    const float px = pos[n * 2 + 0];
    const float py = pos[n * 2 + 1];
    float cx, sx, cy, sy;
    sincosf(px * 64.0f * invf, &sx, &cx);
    sincosf(py * 64.0f * invf, &sy, &cy);
    float* T = &g_trig[(size_t)n * 64];
    T[j] = cx; T[16 + j] = sx; T[32 + j] = cy; T[48 + j] = sy;
}

// ---------------------------------------------------------------------------
// prep: split X and weights into bf16 hi/lo
// ---------------------------------------------------------------------------
__global__ __launch_bounds__(256) void prep_x(const float* __restrict__ X)
{
    const size_t i4 = ((size_t)blockIdx.x * 256 + threadIdx.x) * 4;
    float4 v = *(const float4*)&X[i4];
    __nv_bfloat16 h0, l0, h1, l1, h2, l2, h3, l3;
    bf16split(v.x, h0, l0); bf16split(v.y, h1, l1);
    bf16split(v.z, h2, l2); bf16split(v.w, h3, l3);
    uint2 ph, pl;
    ph.x = (uint32_t)__bfloat16_as_ushort(h0) | ((uint32_t)__bfloat16_as_ushort(h1) << 16);
    ph.y = (uint32_t)__bfloat16_as_ushort(h2) | ((uint32_t)__bfloat16_as_ushort(h3) << 16);
    pl.x = (uint32_t)__bfloat16_as_ushort(l0) | ((uint32_t)__bfloat16_as_ushort(l1) << 16);
    pl.y = (uint32_t)__bfloat16_as_ushort(l2) | ((uint32_t)__bfloat16_as_ushort(l3) << 16);
    *(uint2*)&g_xh[i4] = ph;
    *(uint2*)&g_xl[i4] = pl;
}

__global__ __launch_bounds__(256) void prep_w(
    const float* __restrict__ Wq, const float* __restrict__ Wk,
    const float* __restrict__ Wv, const float* __restrict__ Wo)
{
    const size_t i4 = ((size_t)blockIdx.x * 256 + threadIdx.x) * 4;   // < 524288
    const float* src;
    __nv_bfloat16 *dh, *dl;
    size_t off;
    if (i4 < 393216) {
        int seg = (int)(i4 / 131072);
        off = i4 % 131072;
        src = (seg == 0) ? Wq : (seg == 1) ? Wk : Wv;
        dh = g_wh + (size_t)seg * 131072;
        dl = g_wl + (size_t)seg * 131072;
    } else {
        off = i4 - 393216;
        src = Wo;
        dh = g_woh;
        dl = g_wol;
    }
    float4 v = *(const float4*)&src[off];
    __nv_bfloat16 h0, l0, h1, l1, h2, l2, h3, l3;
    bf16split(v.x, h0, l0); bf16split(v.y, h1, l1);
    bf16split(v.z, h2, l2); bf16split(v.w, h3, l3);
    uint2 ph, pl;
    ph.x = (uint32_t)__bfloat16_as_ushort(h0) | ((uint32_t)__bfloat16_as_ushort(h1) << 16);
    ph.y = (uint32_t)__bfloat16_as_ushort(h2) | ((uint32_t)__bfloat16_as_ushort(h3) << 16);
    pl.x = (uint32_t)__bfloat16_as_ushort(l0) | ((uint32_t)__bfloat16_as_ushort(l1) << 16);
    pl.y = (uint32_t)__bfloat16_as_ushort(l2) | ((uint32_t)__bfloat16_as_ushort(l3) << 16);
    *(uint2*)&dh[off] = ph;
    *(uint2*)&dl[off] = pl;
}

// ---------------------------------------------------------------------------
// HMMA GEMM, single fused K-sweep with hi/lo fragment reuse:
//   D = Ah*Bh + Al*Bh + Ah*Bl   (bf16 2-term split, lo*lo dropped)
// Block tile 128(J) x 128(tok), K slab 32. 8 warps = 4(m) x 2(n), warp 32x64.
// Smem: 4 slabs (Ah, Al, Bh, Bl) 128 x 40(bf16) each = 40960 B static.
// 80B row stride -> ldmatrix conflict-free (banks 20r mod 32 distinct).
// MODE 0: A = W_cat [1536 x 256], B = X [32768 x 256] -> scatter to g_q/g_k/g_v
// MODE 1: A = Wo    [ 256 x 512], B = u [32768 x 512] -> out + bias
// ---------------------------------------------------------------------------
template <int MODE>
__global__ __launch_bounds__(256) void gemm_mma(const float* __restrict__ bias,
                                                float* __restrict__ outp)
{
    constexpr int KTOT = (MODE == 0) ? 256 : 512;
    constexpr int ST = 40;                       // bf16 per smem row (32 + 8 pad)
    constexpr int SLAB = 128 * ST;               // elems per slab

    __shared__ __align__(16) __nv_bfloat16 smem[4 * SLAB];   // 40960 B
    __nv_bfloat16* sAh = smem;
    __nv_bfloat16* sAl = smem + SLAB;
    __nv_bfloat16* sBh = smem + 2 * SLAB;
    __nv_bfloat16* sBl = smem + 3 * SLAB;

    const int tid = threadIdx.x;
    const int wid = tid >> 5;
    const int lane = tid & 31;
    const int wm = wid & 3;        // warp m (J) index: 4
    const int wn = wid >> 2;       // warp n (tok) index: 2
    const int J0 = blockIdx.x * 128;
    const int T0 = blockIdx.y * 128;

    float acc[2][8][4];
    #pragma unroll
    for (int am = 0; am < 2; am++)
        #pragma unroll
        for (int bn = 0; bn < 8; bn++)
            #pragma unroll
            for (int c = 0; c < 4; c++) acc[am][bn][c] = 0.0f;

    const int lrow = tid >> 1;       // 0..127
    const int lhalf = tid & 1;       // 32B half of the 64B slab row

    // fragment smem addresses (constant across slabs)
    const int ar = wm * 32 + (lane & 15);
    const int ac = (lane >> 4) << 3;
    const uint32_t aAh0 = smem_u32(&sAh[(ar)      * ST + ac]);
    const uint32_t aAh1 = smem_u32(&sAh[(ar + 16) * ST + ac]);
    const uint32_t aAl0 = smem_u32(&sAl[(ar)      * ST + ac]);
    const uint32_t aAl1 = smem_u32(&sAl[(ar + 16) * ST + ac]);
    const int br = wn * 64 + ((lane >> 4) << 3) + (lane & 7);
    const int bc = ((lane >> 3) & 1) << 3;
    const uint32_t aBh = smem_u32(&sBh[br * ST + bc]);
    const uint32_t aBl = smem_u32(&sBl[br * ST + bc]);

    for (int kk = 0; kk < KTOT; kk += 32) {
        // stage 4 slabs: each thread = (row, 32B half) per slab
        {
            const __nv_bfloat16 *Ah, *Al, *Bh, *Bl;
            if (MODE == 0) { Ah = g_wh; Al = g_wl; Bh = g_xh; Bl = g_xl; }
            else           { Ah = g_woh; Al = g_wol; Bh = g_uh; Bl = g_ul; }
            const size_t ga = (size_t)(J0 + lrow) * KTOT + kk + lhalf * 16;
            const size_t gb = (size_t)(T0 + lrow) * KTOT + kk + lhalf * 16;
            const int so = lrow * ST + lhalf * 16;
            *(int4*)&sAh[so]     = *(const int4*)&Ah[ga];
            *(int4*)&sAh[so + 8] = *(const int4*)&Ah[ga + 8];
            *(int4*)&sAl[so]     = *(const int4*)&Al[ga];
            *(int4*)&sAl[so + 8] = *(const int4*)&Al[ga + 8];
            *(int4*)&sBh[so]     = *(const int4*)&Bh[gb];
            *(int4*)&sBh[so + 8] = *(const int4*)&Bh[gb + 8];
            *(int4*)&sBl[so]     = *(const int4*)&Bl[gb];
            *(int4*)&sBl[so + 8] = *(const int4*)&Bl[gb + 8];
        }
        __syncthreads();
        #pragma unroll
        for (int ks = 0; ks < 2; ks++) {
            const int co = ks * 16 * 2;          // byte offset col shift: 16 bf16
            uint32_t ah[2][4], al[2][4], bb[8][2];
            ldm_x4(ah[0][0], ah[0][1], ah[0][2], ah[0][3], aAh0 + co);
            ldm_x4(ah[1][0], ah[1][1], ah[1][2], ah[1][3], aAh1 + co);
            ldm_x4(al[0][0], al[0][1], al[0][2], al[0][3], aAl0 + co);
            ldm_x4(al[1][0], al[1][1], al[1][2], al[1][3], aAl1 + co);
            #pragma unroll
            for (int bn = 0; bn < 4; bn++)
                ldm_x4(bb[2 * bn][0], bb[2 * bn][1], bb[2 * bn + 1][0], bb[2 * bn + 1][1],
                       aBh + bn * 16 * ST * 2 + co);
            #pragma unroll
            for (int am = 0; am < 2; am++)
                #pragma unroll
                for (int bn = 0; bn < 8; bn++)
                    mma_bf16(acc[am][bn], ah[am], bb[bn]);
            #pragma unroll
            for (int am = 0; am < 2; am++)
                #pragma unroll
                for (int bn = 0; bn < 8; bn++)
                    mma_bf16(acc[am][bn], al[am], bb[bn]);
            #pragma unroll
            for (int bn = 0; bn < 4; bn++)
                ldm_x4(bb[2 * bn][0], bb[2 * bn][1], bb[2 * bn + 1][0], bb[2 * bn + 1][1],
                       aBl + bn * 16 * ST * 2 + co);
            #pragma unroll
            for (int am = 0; am < 2; am++)
                #pragma unroll
                for (int bn = 0; bn < 8; bn++)
                    mma_bf16(acc[am][bn], ah[am], bb[bn]);
        }
        __syncthreads();
    }

    // Epilogue: two half-passes over tokens, staging transposed in smem.
    float* stage = (float*)smem;   // 64 x 132 fp32 = 33792 B (fits 40960)
    #pragma unroll 1
    for (int half = 0; half < 2; half++) {
        __syncthreads();
        if (wn == half) {
            #pragma unroll
            for (int am = 0; am < 2; am++)
                #pragma unroll
                for (int bn = 0; bn < 8; bn++)
                    #pragma unroll
                    for (int c = 0; c < 4; c++) {
                        const int ml = wm * 32 + am * 16 + (lane >> 2) + ((c >> 1) << 3);
                        const int nl = bn * 8 + (lane & 3) * 2 + (c & 1);
                        stage[nl * 132 + ml] = acc[am][bn][c];
                    }
        }
        __syncthreads();
        const int tok_l = tid >> 2;          // 0..63
        const int qg = tid & 3;              // 32-J group
        const float* srow = &stage[tok_l * 132 + qg * 32];
        const int m = T0 + half * 64 + tok_l;
        const int J = J0 + qg * 32;
        if (MODE == 0) {
            const int which = J >> 9;
            const int h = (J >> 6) & 7;
            const int d = J & 63;
            const int b = m >> 13;
            const int n = m & (NN - 1);
            float* dst = ((which == 0) ? g_q : (which == 1) ? g_k : g_v)
                         + (((size_t)(b * HH + h)) * NN + n) * DD + d;
            #pragma unroll
            for (int dd = 0; dd < 32; dd += 4)
                *(float4*)&dst[dd] = *(const float4*)&srow[dd];
        } else {
            float* dst = outp + (size_t)m * CC + J;
            #pragma unroll
            for (int dd = 0; dd < 32; dd += 4) {
                float4 v = *(const float4*)&srow[dd];
                float4 bv = *(const float4*)&bias[J + dd];
                v.x += bv.x; v.y += bv.y; v.z += bv.z; v.w += bv.w;
                *(float4*)&dst[dd] = v;
            }
        }
    }
}

// ---------------------------------------------------------------------------
// kv_dots: fused instance-norm(K,V) + RoPE(K), partial K^T V per chunk
// ---------------------------------------------------------------------------
__global__ __launch_bounds__(256) void kv_dots()
{
    __shared__ __align__(16) float Ks[16][64];
    __shared__ __align__(16) float Vs[16][64];

    const int chunk = blockIdx.x;
    const int bh = blockIdx.y;
    const int tid = threadIdx.x;
    const int w = tid >> 5;
    const int lane = tid & 31;
    const int jf = lane & 15;
    const float sgn = (lane < 16) ? -1.0f : 1.0f;
    const unsigned FULL = 0xffffffffu;

    const int tx = tid & 15;
    const int ty = tid >> 4;
    const int lt = tid >> 4;
    const int ld4 = (tid & 15) * 4;

    const size_t nbase = (size_t)bh * NN + (size_t)chunk * CHK;

    u64t acc[4][2];
    #pragma unroll
    for (int i = 0; i < 4; i++) { acc[i][0] = 0ull; acc[i][1] = 0ull; }

    for (int s = 0; s < CHK; s += 16) {
        *(float4*)&Ks[lt][ld4] = *(const float4*)&g_k[(nbase + s + lt) * DD + ld4];
        *(float4*)&Vs[lt][ld4] = *(const float4*)&g_v[(nbase + s + lt) * DD + ld4];
        __syncthreads();

        #pragma unroll
        for (int r = 0; r < 2; r++) {
            const int row = w * 2 + r;
            const int n = chunk * CHK + s + row;
            const float* T = &g_trig[(size_t)n * 64];
            const float cx = T[jf], sx = T[16 + jf], cy = T[32 + jf], sy = T[48 + jf];
            {
                float k0 = Ks[row][lane], k1 = Ks[row][32 + lane];
                float su = k0 + k1, ss = k0 * k0 + k1 * k1;
                #pragma unroll
                for (int o = 16; o > 0; o >>= 1) {
                    su += __shfl_xor_sync(FULL, su, o);
                    ss += __shfl_xor_sync(FULL, ss, o);
                }
                float mean = su * (1.0f / 64.0f);
                float var = ss * (1.0f / 64.0f) - mean * mean;
                float inv = rsqrtf(var + 1e-5f);
                k0 = (k0 - mean) * inv;
                k1 = (k1 - mean) * inv;
                float k0p = __shfl_xor_sync(FULL, k0, 16);
                float k1p = __shfl_xor_sync(FULL, k1, 16);
                Ks[row][lane]      = k0 * cx + sgn * k0p * sx;
                Ks[row][32 + lane] = k1 * cy + sgn * k1p * sy;
            }
            {
                float v0 = Vs[row][lane], v1 = Vs[row][32 + lane];
                float su = v0 + v1, ss = v0 * v0 + v1 * v1;
                #pragma unroll
                for (int o = 16; o > 0; o >>= 1) {
                    su += __shfl_xor_sync(FULL, su, o);
                    ss += __shfl_xor_sync(FULL, ss, o);
                }
                float mean = su * (1.0f / 64.0f);
                float var = ss * (1.0f / 64.0f) - mean * mean;
                float inv = rsqrtf(var + 1e-5f);
                Vs[row][lane]      = (v0 - mean) * inv;
                Vs[row][32 + lane] = (v1 - mean) * inv;
            }
        }
        __syncthreads();

        #pragma unroll
        for (int t = 0; t < 16; t++) {
            float4 av = *(const float4*)&Ks[t][ty * 4];
            float4 wv = *(const float4*)&Vs[t][tx * 4];
            u64t w2[2];
            w2[0] = ((const u64t*)&wv)[0];
            w2[1] = ((const u64t*)&wv)[1];
            float a[4] = {av.x, av.y, av.z, av.w};
            #pragma unroll
            for (int i = 0; i < 4; i++) {
                u64t ap = pack2(a[i]);
                acc[i][0] = ffma2(ap, w2[0], acc[i][0]);
                acc[i][1] = ffma2(ap, w2[1], acc[i][1]);
            }
        }
        __syncthreads();
    }

    float* P = &g_part[((size_t)chunk * (BB * HH) + bh) * (DD * DD)];
    #pragma unroll
    for (int i = 0; i < 4; i++) {
        float4 ov;
        unpack2(acc[i][0], ov.x, ov.y);
        unpack2(acc[i][1], ov.z, ov.w);
        *(float4*)&P[(ty * 4 + i) * DD + tx * 4] = ov;
    }
}

__global__ __launch_bounds__(256) void reduce_dots()
{
    const int i = blockIdx.x * 256 + threadIdx.x;
    float s = 0.0f;
    #pragma unroll
    for (int c = 0; c < NCHUNK; c++)
        s += g_part[(size_t)c * (BB * HH * DD * DD) + i];
    g_dots[i] = s * (1.0f / (float)NN);
}

// ---------------------------------------------------------------------------
// q_dots: u = rope(q) @ dots; outputs u as bf16 hi/lo at [m][h*64+d]
// ---------------------------------------------------------------------------
__global__ __launch_bounds__(256) void q_dots()
{
    __shared__ __align__(16) float Qs[64][65];
    __shared__ __align__(16) float Ds[64][64];

    const int bh = blockIdx.y;
    const int n0 = blockIdx.x * 64;
    const int tid = threadIdx.x;
    const int w = tid >> 5;
    const int lane = tid & 31;
    const int jf = lane & 15;
    const float sgn = (lane < 16) ? -1.0f : 1.0f;
    const unsigned FULL = 0xffffffffu;

    const int lt = tid >> 4;
    const int ld4 = (tid & 15) * 4;
    #pragma unroll
    for (int r = 0; r < 4; r++)
        *(float4*)&Ds[lt + 16 * r][ld4] =
            *(const float4*)&g_dots[(size_t)bh * (DD * DD) + (lt + 16 * r) * DD + ld4];

    #pragma unroll
    for (int r = 0; r < 8; r++) {
        const int trow = w * 8 + r;
        const int n = n0 + trow;
        const float* T = &g_trig[(size_t)n * 64];
        const float cx = T[jf], sx = T[16 + jf], cy = T[32 + jf], sy = T[48 + jf];
        const size_t base = ((size_t)bh * NN + n) * DD;
        float q0 = g_q[base + lane];
        float q1 = g_q[base + 32 + lane];
        float q0p = __shfl_xor_sync(FULL, q0, 16);
        float q1p = __shfl_xor_sync(FULL, q1, 16);
        Qs[trow][lane]      = q0 * cx + sgn * q0p * sx;
        Qs[trow][32 + lane] = q1 * cy + sgn * q1p * sy;
    }
    __syncthreads();

    const int tx = tid & 15;
    const int ty = tid >> 4;
    u64t acc[4][2];
    #pragma unroll
    for (int i = 0; i < 4; i++) { acc[i][0] = 0ull; acc[i][1] = 0ull; }

    #pragma unroll 4
    for (int k = 0; k < 64; k++) {
        float4 wv = *(const float4*)&Ds[k][tx * 4];
        u64t w2[2];
        w2[0] = ((const u64t*)&wv)[0];
        w2[1] = ((const u64t*)&wv)[1];
        #pragma unroll
        for (int i = 0; i < 4; i++) {
            u64t ap = pack2(Qs[ty * 4 + i][k]);
            acc[i][0] = ffma2(ap, w2[0], acc[i][0]);
            acc[i][1] = ffma2(ap, w2[1], acc[i][1]);
        }
    }

    const int b = bh >> 3;
    const int h = bh & 7;
    #pragma unroll
    for (int i = 0; i < 4; i++) {
        float4 ov;
        unpack2(acc[i][0], ov.x, ov.y);
        unpack2(acc[i][1], ov.z, ov.w);
        const size_t m = (size_t)b * NN + (n0 + ty * 4 + i);
        const size_t off = m * HD + h * DD + tx * 4;
        __nv_bfloat16 h0, l0, h1, l1, h2, l2, h3, l3;
        bf16split(ov.x, h0, l0); bf16split(ov.y, h1, l1);
        bf16split(ov.z, h2, l2); bf16split(ov.w, h3, l3);
        uint2 ph, pl;
        ph.x = (uint32_t)__bfloat16_as_ushort(h0) | ((uint32_t)__bfloat16_as_ushort(h1) << 16);
        ph.y = (uint32_t)__bfloat16_as_ushort(h2) | ((uint32_t)__bfloat16_as_ushort(h3) << 16);
        pl.x = (uint32_t)__bfloat16_as_ushort(l0) | ((uint32_t)__bfloat16_as_ushort(l1) << 16);
        pl.y = (uint32_t)__bfloat16_as_ushort(l2) | ((uint32_t)__bfloat16_as_ushort(l3) << 16);
        *(uint2*)&g_uh[off] = ph;
        *(uint2*)&g_ul[off] = pl;
    }
}

// ---------------------------------------------------------------------------
extern "C" void kernel_launch(void* const* d_in, const int* in_sizes, int n_in,
                              void* d_out, int out_size)
{
    const float* ux  = (const float*)d_in[0];
    const float* pos = (const float*)d_in[1];
    const float* Wq  = (const float*)d_in[2];
    const float* Wk  = (const float*)d_in[3];
    const float* Wv  = (const float*)d_in[4];
    const float* Wo  = (const float*)d_in[5];
    const float* bo  = (const float*)d_in[6];
    float* out = (float*)d_out;

    trig_init<<<(NN * 16) / 256, 256>>>(pos);
    prep_x<<<(32768 * 256) / (256 * 4), 256>>>(ux);
    prep_w<<<524288 / (256 * 4), 256>>>(Wq, Wk, Wv, Wo);
    gemm_mma<0><<<dim3(12, 256), 256>>>(nullptr, nullptr);
    kv_dots<<<dim3(NCHUNK, BB * HH), 256>>>();
    reduce_dots<<<(BB * HH * DD * DD) / 256, 256>>>();
    q_dots<<<dim3(NN / 64, BB * HH), 256>>>();
    gemm_mma<1><<<dim3(2, 256), 256>>>(bo, out);
}

// round 11
// speedup vs baseline: 1.1950x; 1.1950x over previous
#include <cuda_runtime.h>
#include <cuda_bf16.h>
#include <math.h>
#include <stdint.h>

#define BB 4
#define NN 8192
#define CC 256
#define HH 8
#define DD 64
#define HD 512
#define NCHUNK 16
#define CHK (NN / NCHUNK)   // 512

typedef unsigned long long u64t;

// ---------------------------------------------------------------------------
// Scratch (__device__ globals; allocation-free rule)
// ---------------------------------------------------------------------------
__device__ float g_q[BB * HH * NN * DD];            // [bh][n][d] fp32
__device__ float g_k[BB * HH * NN * DD];
__device__ float g_v[BB * HH * NN * DD];
__device__ float g_part[NCHUNK * BB * HH * DD * DD];
__device__ float g_dots[BB * HH * DD * DD];
__device__ float g_trig[NN * 64];                   // per n: cx[16] sx[16] cy[16] sy[16]

__device__ __nv_bfloat16 g_xh[32768 * 256];         // X split
__device__ __nv_bfloat16 g_xl[32768 * 256];
__device__ __nv_bfloat16 g_wh[1536 * 256];          // [Wq;Wk;Wv] split
__device__ __nv_bfloat16 g_wl[1536 * 256];
__device__ __nv_bfloat16 g_woh[256 * 512];          // Wo split
__device__ __nv_bfloat16 g_wol[256 * 512];
__device__ __nv_bfloat16 g_uh[32768 * 512];         // u split, [m][h*64+d]
__device__ __nv_bfloat16 g_ul[32768 * 512];

// ---------------------------------------------------------------------------
// helpers
// ---------------------------------------------------------------------------
__device__ __forceinline__ uint32_t smem_u32(const void* p) {
    uint32_t a;
    asm("{ .reg .u64 t; cvta.to.shared.u64 t, %1; cvt.u32.u64 %0, t; }" : "=r"(a) : "l"(p));
    return a;
}
__device__ __forceinline__ void ldm_x4(uint32_t& r0, uint32_t& r1, uint32_t& r2, uint32_t& r3,
                                       uint32_t addr) {
    asm volatile("ldmatrix.sync.aligned.m8n8.x4.shared.b16 {%0,%1,%2,%3}, [%4];"
                 : "=r"(r0), "=r"(r1), "=r"(r2), "=r"(r3) : "r"(addr));
}
__device__ __forceinline__ void mma_bf16(float* d, const uint32_t* a, const uint32_t* b) {
    asm volatile(
        "mma.sync.aligned.m16n8k16.row.col.f32.bf16.bf16.f32 "
        "{%0,%1,%2,%3}, {%4,%5,%6,%7}, {%8,%9}, {%0,%1,%2,%3};"
        : "+f"(d[0]), "+f"(d[1]), "+f"(d[2]), "+f"(d[3])
        : "r"(a[0]), "r"(a[1]), "r"(a[2]), "r"(a[3]), "r"(b[0]), "r"(b[1]));
}

// ---- packed f32x2 helpers (SIMT kernels) ----------------------------------
__device__ __forceinline__ u64t ffma2(u64t a, u64t b, u64t c) {
    u64t d;
    asm("fma.rn.f32x2 %0, %1, %2, %3;" : "=l"(d) : "l"(a), "l"(b), "l"(c));
    return d;
}
__device__ __forceinline__ u64t pack2(float x) {
    u64t d;
    asm("mov.b64 %0, {%1, %1};" : "=l"(d) : "r"(__float_as_uint(x)));
    return d;
}
__device__ __forceinline__ void unpack2(u64t v, float& lo, float& hi) {
    unsigned a, b;
    asm("mov.b64 {%0, %1}, %2;" : "=r"(a), "=r"(b) : "l"(v));
    lo = __uint_as_float(a);
    hi = __uint_as_float(b);
}
__device__ __forceinline__ void bf16split(float x, __nv_bfloat16& h, __nv_bfloat16& l) {
    h = __float2bfloat16_rn(x);
    l = __float2bfloat16_rn(x - __bfloat162float(h));
}

// ---------------------------------------------------------------------------
// trig table
// ---------------------------------------------------------------------------
__global__ __launch_bounds__(256) void trig_init(const float* __restrict__ pos)
{
    const int idx = blockIdx.x * 256 + threadIdx.x;
    const int n = idx >> 4;
    const int j = idx & 15;
    const float invf = exp2f(-(float)j * (13.2877123795494f / 16.0f));
    const float px = pos[n * 2 + 0];
    const float py = pos[n * 2 + 1];
    float cx, sx, cy, sy;
    sincosf(px * 64.0f * invf, &sx, &cx);
    sincosf(py * 64.0f * invf, &sy, &cy);
    float* T = &g_trig[(size_t)n * 64];
    T[j] = cx; T[16 + j] = sx; T[32 + j] = cy; T[48 + j] = sy;
}

// ---------------------------------------------------------------------------
// prep: split X and weights into bf16 hi/lo
// ---------------------------------------------------------------------------
__global__ __launch_bounds__(256) void prep_x(const float* __restrict__ X)
{
    const size_t i4 = ((size_t)blockIdx.x * 256 + threadIdx.x) * 4;
    float4 v = *(const float4*)&X[i4];
    __nv_bfloat16 h0, l0, h1, l1, h2, l2, h3, l3;
    bf16split(v.x, h0, l0); bf16split(v.y, h1, l1);
    bf16split(v.z, h2, l2); bf16split(v.w, h3, l3);
    uint2 ph, pl;
    ph.x = (uint32_t)__bfloat16_as_ushort(h0) | ((uint32_t)__bfloat16_as_ushort(h1) << 16);
    ph.y = (uint32_t)__bfloat16_as_ushort(h2) | ((uint32_t)__bfloat16_as_ushort(h3) << 16);
    pl.x = (uint32_t)__bfloat16_as_ushort(l0) | ((uint32_t)__bfloat16_as_ushort(l1) << 16);
    pl.y = (uint32_t)__bfloat16_as_ushort(l2) | ((uint32_t)__bfloat16_as_ushort(l3) << 16);
    *(uint2*)&g_xh[i4] = ph;
    *(uint2*)&g_xl[i4] = pl;
}

__global__ __launch_bounds__(256) void prep_w(
    const float* __restrict__ Wq, const float* __restrict__ Wk,
    const float* __restrict__ Wv, const float* __restrict__ Wo)
{
    const size_t i4 = ((size_t)blockIdx.x * 256 + threadIdx.x) * 4;   // < 524288
    const float* src;
    __nv_bfloat16 *dh, *dl;
    size_t off;
    if (i4 < 393216) {
        int seg = (int)(i4 / 131072);
        off = i4 % 131072;
        src = (seg == 0) ? Wq : (seg == 1) ? Wk : Wv;
        dh = g_wh + (size_t)seg * 131072;
        dl = g_wl + (size_t)seg * 131072;
    } else {
        off = i4 - 393216;
        src = Wo;
        dh = g_woh;
        dl = g_wol;
    }
    float4 v = *(const float4*)&src[off];
    __nv_bfloat16 h0, l0, h1, l1, h2, l2, h3, l3;
    bf16split(v.x, h0, l0); bf16split(v.y, h1, l1);
    bf16split(v.z, h2, l2); bf16split(v.w, h3, l3);
    uint2 ph, pl;
    ph.x = (uint32_t)__bfloat16_as_ushort(h0) | ((uint32_t)__bfloat16_as_ushort(h1) << 16);
    ph.y = (uint32_t)__bfloat16_as_ushort(h2) | ((uint32_t)__bfloat16_as_ushort(h3) << 16);
    pl.x = (uint32_t)__bfloat16_as_ushort(l0) | ((uint32_t)__bfloat16_as_ushort(l1) << 16);
    pl.y = (uint32_t)__bfloat16_as_ushort(l2) | ((uint32_t)__bfloat16_as_ushort(l3) << 16);
    *(uint2*)&dh[off] = ph;
    *(uint2*)&dl[off] = pl;
}

// ---------------------------------------------------------------------------
// HMMA GEMM, single fused K-sweep with hi/lo fragment reuse:
//   D = Ah*Bh + Al*Bh + Ah*Bl   (bf16 2-term split, lo*lo dropped)
// Block tile 128(J) x 128(tok), K slab 32. 8 warps = 4(m) x 2(n), warp 32x64.
// B fragments processed in two bn-halves (bb[4][2]) to keep natural register
// demand ~110 (R8's 138-reg/1-CTA occupancy collapse; R9's forced-128 spill
// schedule both avoided). __launch_bounds__(256, 2) keeps the 2-CTA guarantee.
// Smem: 4 slabs (Ah, Al, Bh, Bl) 128 x 40(bf16) each = 40960 B static.
// MODE 0: A = W_cat [1536 x 256], B = X [32768 x 256] -> scatter to g_q/g_k/g_v
// MODE 1: A = Wo    [ 256 x 512], B = u [32768 x 512] -> out + bias
// ---------------------------------------------------------------------------
template <int MODE>
__global__ __launch_bounds__(256, 2) void gemm_mma(const float* __restrict__ bias,
                                                   float* __restrict__ outp)
{
    constexpr int KTOT = (MODE == 0) ? 256 : 512;
    constexpr int ST = 40;                       // bf16 per smem row (32 + 8 pad)
    constexpr int SLAB = 128 * ST;               // elems per slab

    __shared__ __align__(16) __nv_bfloat16 smem[4 * SLAB];   // 40960 B
    __nv_bfloat16* sAh = smem;
    __nv_bfloat16* sAl = smem + SLAB;
    __nv_bfloat16* sBh = smem + 2 * SLAB;
    __nv_bfloat16* sBl = smem + 3 * SLAB;

    const int tid = threadIdx.x;
    const int wid = tid >> 5;
    const int lane = tid & 31;
    const int wm = wid & 3;        // warp m (J) index: 4
    const int wn = wid >> 2;       // warp n (tok) index: 2
    const int J0 = blockIdx.x * 128;
    const int T0 = blockIdx.y * 128;

    float acc[2][8][4];
    #pragma unroll
    for (int am = 0; am < 2; am++)
        #pragma unroll
        for (int bn = 0; bn < 8; bn++)
            #pragma unroll
            for (int c = 0; c < 4; c++) acc[am][bn][c] = 0.0f;

    const int lrow = tid >> 1;       // 0..127
    const int lhalf = tid & 1;       // 32B half of the 64B slab row

    // fragment smem addresses (constant across slabs)
    const int ar = wm * 32 + (lane & 15);
    const int ac = (lane >> 4) << 3;
    const uint32_t aAh0 = smem_u32(&sAh[(ar)      * ST + ac]);
    const uint32_t aAh1 = smem_u32(&sAh[(ar + 16) * ST + ac]);
    const uint32_t aAl0 = smem_u32(&sAl[(ar)      * ST + ac]);
    const uint32_t aAl1 = smem_u32(&sAl[(ar + 16) * ST + ac]);
    const int br = wn * 64 + ((lane >> 4) << 3) + (lane & 7);
    const int bc = ((lane >> 3) & 1) << 3;
    const uint32_t aBh = smem_u32(&sBh[br * ST + bc]);
    const uint32_t aBl = smem_u32(&sBl[br * ST + bc]);

    for (int kk = 0; kk < KTOT; kk += 32) {
        // stage 4 slabs: each thread = (row, 32B half) per slab
        {
            const __nv_bfloat16 *Ah, *Al, *Bh, *Bl;
            if (MODE == 0) { Ah = g_wh; Al = g_wl; Bh = g_xh; Bl = g_xl; }
            else           { Ah = g_woh; Al = g_wol; Bh = g_uh; Bl = g_ul; }
            const size_t ga = (size_t)(J0 + lrow) * KTOT + kk + lhalf * 16;
            const size_t gb = (size_t)(T0 + lrow) * KTOT + kk + lhalf * 16;
            const int so = lrow * ST + lhalf * 16;
            *(int4*)&sAh[so]     = *(const int4*)&Ah[ga];
            *(int4*)&sAh[so + 8] = *(const int4*)&Ah[ga + 8];
            *(int4*)&sAl[so]     = *(const int4*)&Al[ga];
            *(int4*)&sAl[so + 8] = *(const int4*)&Al[ga + 8];
            *(int4*)&sBh[so]     = *(const int4*)&Bh[gb];
            *(int4*)&sBh[so + 8] = *(const int4*)&Bh[gb + 8];
            *(int4*)&sBl[so]     = *(const int4*)&Bl[gb];
            *(int4*)&sBl[so + 8] = *(const int4*)&Bl[gb + 8];
        }
        __syncthreads();
        #pragma unroll
        for (int ks = 0; ks < 2; ks++) {
            const int co = ks * 16 * 2;          // byte offset col shift: 16 bf16
            uint32_t ah[2][4], al[2][4];
            ldm_x4(ah[0][0], ah[0][1], ah[0][2], ah[0][3], aAh0 + co);
            ldm_x4(ah[1][0], ah[1][1], ah[1][2], ah[1][3], aAh1 + co);
            ldm_x4(al[0][0], al[0][1], al[0][2], al[0][3], aAl0 + co);
            ldm_x4(al[1][0], al[1][1], al[1][2], al[1][3], aAl1 + co);
            #pragma unroll
            for (int h2 = 0; h2 < 2; h2++) {     // bn half: fragments 4*h2 .. 4*h2+3
                uint32_t bb[4][2];
                #pragma unroll
                for (int j = 0; j < 2; j++)
                    ldm_x4(bb[2 * j][0], bb[2 * j][1], bb[2 * j + 1][0], bb[2 * j + 1][1],
                           aBh + (2 * h2 + j) * 16 * ST * 2 + co);
                #pragma unroll
                for (int am = 0; am < 2; am++)
                    #pragma unroll
                    for (int j4 = 0; j4 < 4; j4++)
                        mma_bf16(acc[am][4 * h2 + j4], ah[am], bb[j4]);
                #pragma unroll
                for (int am = 0; am < 2; am++)
                    #pragma unroll
                    for (int j4 = 0; j4 < 4; j4++)
                        mma_bf16(acc[am][4 * h2 + j4], al[am], bb[j4]);
                #pragma unroll
                for (int j = 0; j < 2; j++)
                    ldm_x4(bb[2 * j][0], bb[2 * j][1], bb[2 * j + 1][0], bb[2 * j + 1][1],
                           aBl + (2 * h2 + j) * 16 * ST * 2 + co);
                #pragma unroll
                for (int am = 0; am < 2; am++)
                    #pragma unroll
                    for (int j4 = 0; j4 < 4; j4++)
                        mma_bf16(acc[am][4 * h2 + j4], ah[am], bb[j4]);
            }
        }
        __syncthreads();
    }

    // Epilogue: two half-passes over tokens, staging transposed in smem.
    float* stage = (float*)smem;   // 64 x 132 fp32 = 33792 B (fits 40960)
    #pragma unroll 1
    for (int half = 0; half < 2; half++) {
        __syncthreads();
        if (wn == half) {
            #pragma unroll
            for (int am = 0; am < 2; am++)
                #pragma unroll
                for (int bn = 0; bn < 8; bn++)
                    #pragma unroll
                    for (int c = 0; c < 4; c++) {
                        const int ml = wm * 32 + am * 16 + (lane >> 2) + ((c >> 1) << 3);
                        const int nl = bn * 8 + (lane & 3) * 2 + (c & 1);
                        stage[nl * 132 + ml] = acc[am][bn][c];
                    }
        }
        __syncthreads();
        const int tok_l = tid >> 2;          // 0..63
        const int qg = tid & 3;              // 32-J group
        const float* srow = &stage[tok_l * 132 + qg * 32];
        const int m = T0 + half * 64 + tok_l;
        const int J = J0 + qg * 32;
        if (MODE == 0) {
            const int which = J >> 9;
            const int h = (J >> 6) & 7;
            const int d = J & 63;
            const int b = m >> 13;
            const int n = m & (NN - 1);
            float* dst = ((which == 0) ? g_q : (which == 1) ? g_k : g_v)
                         + (((size_t)(b * HH + h)) * NN + n) * DD + d;
            #pragma unroll
            for (int dd = 0; dd < 32; dd += 4)
                *(float4*)&dst[dd] = *(const float4*)&srow[dd];
        } else {
            float* dst = outp + (size_t)m * CC + J;
            #pragma unroll
            for (int dd = 0; dd < 32; dd += 4) {
                float4 v = *(const float4*)&srow[dd];
                float4 bv = *(const float4*)&bias[J + dd];
                v.x += bv.x; v.y += bv.y; v.z += bv.z; v.w += bv.w;
                *(float4*)&dst[dd] = v;
            }
        }
    }
}

// ---------------------------------------------------------------------------
// kv_dots: fused instance-norm(K,V) + RoPE(K), partial K^T V per chunk
// ---------------------------------------------------------------------------
__global__ __launch_bounds__(256) void kv_dots()
{
    __shared__ __align__(16) float Ks[16][64];
    __shared__ __align__(16) float Vs[16][64];

    const int chunk = blockIdx.x;
    const int bh = blockIdx.y;
    const int tid = threadIdx.x;
    const int w = tid >> 5;
    const int lane = tid & 31;
    const int jf = lane & 15;
    const float sgn = (lane < 16) ? -1.0f : 1.0f;
    const unsigned FULL = 0xffffffffu;

    const int tx = tid & 15;
    const int ty = tid >> 4;
    const int lt = tid >> 4;
    const int ld4 = (tid & 15) * 4;

    const size_t nbase = (size_t)bh * NN + (size_t)chunk * CHK;

    u64t acc[4][2];
    #pragma unroll
    for (int i = 0; i < 4; i++) { acc[i][0] = 0ull; acc[i][1] = 0ull; }

    for (int s = 0; s < CHK; s += 16) {
        *(float4*)&Ks[lt][ld4] = *(const float4*)&g_k[(nbase + s + lt) * DD + ld4];
        *(float4*)&Vs[lt][ld4] = *(const float4*)&g_v[(nbase + s + lt) * DD + ld4];
        __syncthreads();

        #pragma unroll
        for (int r = 0; r < 2; r++) {
            const int row = w * 2 + r;
            const int n = chunk * CHK + s + row;
            const float* T = &g_trig[(size_t)n * 64];
            const float cx = T[jf], sx = T[16 + jf], cy = T[32 + jf], sy = T[48 + jf];
            {
                float k0 = Ks[row][lane], k1 = Ks[row][32 + lane];
                float su = k0 + k1, ss = k0 * k0 + k1 * k1;
                #pragma unroll
                for (int o = 16; o > 0; o >>= 1) {
                    su += __shfl_xor_sync(FULL, su, o);
                    ss += __shfl_xor_sync(FULL, ss, o);
                }
                float mean = su * (1.0f / 64.0f);
                float var = ss * (1.0f / 64.0f) - mean * mean;
                float inv = rsqrtf(var + 1e-5f);
                k0 = (k0 - mean) * inv;
                k1 = (k1 - mean) * inv;
                float k0p = __shfl_xor_sync(FULL, k0, 16);
                float k1p = __shfl_xor_sync(FULL, k1, 16);
                Ks[row][lane]      = k0 * cx + sgn * k0p * sx;
                Ks[row][32 + lane] = k1 * cy + sgn * k1p * sy;
            }
            {
                float v0 = Vs[row][lane], v1 = Vs[row][32 + lane];
                float su = v0 + v1, ss = v0 * v0 + v1 * v1;
                #pragma unroll
                for (int o = 16; o > 0; o >>= 1) {
                    su += __shfl_xor_sync(FULL, su, o);
                    ss += __shfl_xor_sync(FULL, ss, o);
                }
                float mean = su * (1.0f / 64.0f);
                float var = ss * (1.0f / 64.0f) - mean * mean;
                float inv = rsqrtf(var + 1e-5f);
                Vs[row][lane]      = (v0 - mean) * inv;
                Vs[row][32 + lane] = (v1 - mean) * inv;
            }
        }
        __syncthreads();

        #pragma unroll
        for (int t = 0; t < 16; t++) {
            float4 av = *(const float4*)&Ks[t][ty * 4];
            float4 wv = *(const float4*)&Vs[t][tx * 4];
            u64t w2[2];
            w2[0] = ((const u64t*)&wv)[0];
            w2[1] = ((const u64t*)&wv)[1];
            float a[4] = {av.x, av.y, av.z, av.w};
            #pragma unroll
            for (int i = 0; i < 4; i++) {
                u64t ap = pack2(a[i]);
                acc[i][0] = ffma2(ap, w2[0], acc[i][0]);
                acc[i][1] = ffma2(ap, w2[1], acc[i][1]);
            }
        }
        __syncthreads();
    }

    float* P = &g_part[((size_t)chunk * (BB * HH) + bh) * (DD * DD)];
    #pragma unroll
    for (int i = 0; i < 4; i++) {
        float4 ov;
        unpack2(acc[i][0], ov.x, ov.y);
        unpack2(acc[i][1], ov.z, ov.w);
        *(float4*)&P[(ty * 4 + i) * DD + tx * 4] = ov;
    }
}

__global__ __launch_bounds__(256) void reduce_dots()
{
    const int i = blockIdx.x * 256 + threadIdx.x;
    float s = 0.0f;
    #pragma unroll
    for (int c = 0; c < NCHUNK; c++)
        s += g_part[(size_t)c * (BB * HH * DD * DD) + i];
    g_dots[i] = s * (1.0f / (float)NN);
}

// ---------------------------------------------------------------------------
// q_dots: u = rope(q) @ dots; outputs u as bf16 hi/lo at [m][h*64+d]
// ---------------------------------------------------------------------------
__global__ __launch_bounds__(256) void q_dots()
{
    __shared__ __align__(16) float Qs[64][65];
    __shared__ __align__(16) float Ds[64][64];

    const int bh = blockIdx.y;
    const int n0 = blockIdx.x * 64;
    const int tid = threadIdx.x;
    const int w = tid >> 5;
    const int lane = tid & 31;
    const int jf = lane & 15;
    const float sgn = (lane < 16) ? -1.0f : 1.0f;
    const unsigned FULL = 0xffffffffu;

    const int lt = tid >> 4;
    const int ld4 = (tid & 15) * 4;
    #pragma unroll
    for (int r = 0; r < 4; r++)
        *(float4*)&Ds[lt + 16 * r][ld4] =
            *(const float4*)&g_dots[(size_t)bh * (DD * DD) + (lt + 16 * r) * DD + ld4];

    #pragma unroll
    for (int r = 0; r < 8; r++) {
        const int trow = w * 8 + r;
        const int n = n0 + trow;
        const float* T = &g_trig[(size_t)n * 64];
        const float cx = T[jf], sx = T[16 + jf], cy = T[32 + jf], sy = T[48 + jf];
        const size_t base = ((size_t)bh * NN + n) * DD;
        float q0 = g_q[base + lane];
        float q1 = g_q[base + 32 + lane];
        float q0p = __shfl_xor_sync(FULL, q0, 16);
        float q1p = __shfl_xor_sync(FULL, q1, 16);
        Qs[trow][lane]      = q0 * cx + sgn * q0p * sx;
        Qs[trow][32 + lane] = q1 * cy + sgn * q1p * sy;
    }
    __syncthreads();

    const int tx = tid & 15;
    const int ty = tid >> 4;
    u64t acc[4][2];
    #pragma unroll
    for (int i = 0; i < 4; i++) { acc[i][0] = 0ull; acc[i][1] = 0ull; }

    #pragma unroll 4
    for (int k = 0; k < 64; k++) {
        float4 wv = *(const float4*)&Ds[k][tx * 4];
        u64t w2[2];
        w2[0] = ((const u64t*)&wv)[0];
        w2[1] = ((const u64t*)&wv)[1];
        #pragma unroll
        for (int i = 0; i < 4; i++) {
            u64t ap = pack2(Qs[ty * 4 + i][k]);
            acc[i][0] = ffma2(ap, w2[0], acc[i][0]);
            acc[i][1] = ffma2(ap, w2[1], acc[i][1]);
        }
    }

    const int b = bh >> 3;
    const int h = bh & 7;
    #pragma unroll
    for (int i = 0; i < 4; i++) {
        float4 ov;
        unpack2(acc[i][0], ov.x, ov.y);
        unpack2(acc[i][1], ov.z, ov.w);
        const size_t m = (size_t)b * NN + (n0 + ty * 4 + i);
        const size_t off = m * HD + h * DD + tx * 4;
        __nv_bfloat16 h0, l0, h1, l1, h2, l2, h3, l3;
        bf16split(ov.x, h0, l0); bf16split(ov.y, h1, l1);
        bf16split(ov.z, h2, l2); bf16split(ov.w, h3, l3);
        uint2 ph, pl;
        ph.x = (uint32_t)__bfloat16_as_ushort(h0) | ((uint32_t)__bfloat16_as_ushort(h1) << 16);
        ph.y = (uint32_t)__bfloat16_as_ushort(h2) | ((uint32_t)__bfloat16_as_ushort(h3) << 16);
        pl.x = (uint32_t)__bfloat16_as_ushort(l0) | ((uint32_t)__bfloat16_as_ushort(l1) << 16);
        pl.y = (uint32_t)__bfloat16_as_ushort(l2) | ((uint32_t)__bfloat16_as_ushort(l3) << 16);
        *(uint2*)&g_uh[off] = ph;
        *(uint2*)&g_ul[off] = pl;
    }
}

// ---------------------------------------------------------------------------
extern "C" void kernel_launch(void* const* d_in, const int* in_sizes, int n_in,
                              void* d_out, int out_size)
{
    const float* ux  = (const float*)d_in[0];
    const float* pos = (const float*)d_in[1];
    const float* Wq  = (const float*)d_in[2];
    const float* Wk  = (const float*)d_in[3];
    const float* Wv  = (const float*)d_in[4];
    const float* Wo  = (const float*)d_in[5];
    const float* bo  = (const float*)d_in[6];
    float* out = (float*)d_out;

    trig_init<<<(NN * 16) / 256, 256>>>(pos);
    prep_x<<<(32768 * 256) / (256 * 4), 256>>>(ux);
    prep_w<<<524288 / (256 * 4), 256>>>(Wq, Wk, Wv, Wo);
    gemm_mma<0><<<dim3(12, 256), 256>>>(nullptr, nullptr);
    kv_dots<<<dim3(NCHUNK, BB * HH), 256>>>();
    reduce_dots<<<(BB * HH * DD * DD) / 256, 256>>>();
    q_dots<<<dim3(NN / 64, BB * HH), 256>>>();
    gemm_mma<1><<<dim3(2, 256), 256>>>(bo, out);
}

// round 13
// speedup vs baseline: 1.2530x; 1.0485x over previous
#include <cuda_runtime.h>
#include <cuda_bf16.h>
#include <math.h>
#include <stdint.h>

#define BB 4
#define NN 8192
#define CC 256
#define HH 8
#define DD 64
#define HD 512
#define NCHUNK 16
#define CHK (NN / NCHUNK)   // 512

typedef unsigned long long u64t;

// ---------------------------------------------------------------------------
// Scratch (__device__ globals; allocation-free rule)
// ---------------------------------------------------------------------------
__device__ float g_q[BB * HH * NN * DD];            // [bh][n][d] fp32
__device__ float g_k[BB * HH * NN * DD];
__device__ float g_v[BB * HH * NN * DD];
__device__ float g_part[NCHUNK * BB * HH * DD * DD];
__device__ float g_dots[BB * HH * DD * DD];
__device__ float g_trig[NN * 64];                   // per n: cx[16] sx[16] cy[16] sy[16]

__device__ __nv_bfloat16 g_xh[32768 * 256];         // X split
__device__ __nv_bfloat16 g_xl[32768 * 256];
__device__ __nv_bfloat16 g_wh[1536 * 256];          // [Wq;Wk;Wv] split
__device__ __nv_bfloat16 g_wl[1536 * 256];
__device__ __nv_bfloat16 g_woh[256 * 512];          // Wo split
__device__ __nv_bfloat16 g_wol[256 * 512];
__device__ __nv_bfloat16 g_uh[32768 * 512];         // u split, [m][h*64+d]
__device__ __nv_bfloat16 g_ul[32768 * 512];

// ---------------------------------------------------------------------------
// helpers
// ---------------------------------------------------------------------------
__device__ __forceinline__ uint32_t smem_u32(const void* p) {
    uint32_t a;
    asm("{ .reg .u64 t; cvta.to.shared.u64 t, %1; cvt.u32.u64 %0, t; }" : "=r"(a) : "l"(p));
    return a;
}
__device__ __forceinline__ void ldm_x4(uint32_t& r0, uint32_t& r1, uint32_t& r2, uint32_t& r3,
                                       uint32_t addr) {
    asm volatile("ldmatrix.sync.aligned.m8n8.x4.shared.b16 {%0,%1,%2,%3}, [%4];"
                 : "=r"(r0), "=r"(r1), "=r"(r2), "=r"(r3) : "r"(addr));
}
__device__ __forceinline__ void mma_bf16(float* d, const uint32_t* a, const uint32_t* b) {
    asm volatile(
        "mma.sync.aligned.m16n8k16.row.col.f32.bf16.bf16.f32 "
        "{%0,%1,%2,%3}, {%4,%5,%6,%7}, {%8,%9}, {%0,%1,%2,%3};"
        : "+f"(d[0]), "+f"(d[1]), "+f"(d[2]), "+f"(d[3])
        : "r"(a[0]), "r"(a[1]), "r"(a[2]), "r"(a[3]), "r"(b[0]), "r"(b[1]));
}
// cp.async: global -> smem direct, bypassing the register file / L1 writeback.
__device__ __forceinline__ void cp_async16(uint32_t smem_addr, const void* gptr) {
    asm volatile("cp.async.cg.shared.global [%0], [%1], 16;"
                 :: "r"(smem_addr), "l"(gptr) : "memory");
}
#define CP_ASYNC_COMMIT() asm volatile("cp.async.commit_group;" ::: "memory")
#define CP_ASYNC_WAIT0()  asm volatile("cp.async.wait_group 0;" ::: "memory")

// ---- packed f32x2 helpers (SIMT kernels) ----------------------------------
__device__ __forceinline__ u64t ffma2(u64t a, u64t b, u64t c) {
    u64t d;
    asm("fma.rn.f32x2 %0, %1, %2, %3;" : "=l"(d) : "l"(a), "l"(b), "l"(c));
    return d;
}
__device__ __forceinline__ u64t pack2(float x) {
    u64t d;
    asm("mov.b64 %0, {%1, %1};" : "=l"(d) : "r"(__float_as_uint(x)));
    return d;
}
__device__ __forceinline__ void unpack2(u64t v, float& lo, float& hi) {
    unsigned a, b;
    asm("mov.b64 {%0, %1}, %2;" : "=r"(a), "=r"(b) : "l"(v));
    lo = __uint_as_float(a);
    hi = __uint_as_float(b);
}
__device__ __forceinline__ void bf16split(float x, __nv_bfloat16& h, __nv_bfloat16& l) {
    h = __float2bfloat16_rn(x);
    l = __float2bfloat16_rn(x - __bfloat162float(h));
}

// ---------------------------------------------------------------------------
// trig table
// ---------------------------------------------------------------------------
__global__ __launch_bounds__(256) void trig_init(const float* __restrict__ pos)
{
    const int idx = blockIdx.x * 256 + threadIdx.x;
    const int n = idx >> 4;
    const int j = idx & 15;
    const float invf = exp2f(-(float)j * (13.2877123795494f / 16.0f));
    const float px = pos[n * 2 + 0];
    const float py = pos[n * 2 + 1];
    float cx, sx, cy, sy;
    sincosf(px * 64.0f * invf, &sx, &cx);
    sincosf(py * 64.0f * invf, &sy, &cy);
    float* T = &g_trig[(size_t)n * 64];
    T[j] = cx; T[16 + j] = sx; T[32 + j] = cy; T[48 + j] = sy;
}

// ---------------------------------------------------------------------------
// prep: split X and weights into bf16 hi/lo
// ---------------------------------------------------------------------------
__global__ __launch_bounds__(256) void prep_x(const float* __restrict__ X)
{
    const size_t i4 = ((size_t)blockIdx.x * 256 + threadIdx.x) * 4;
    float4 v = *(const float4*)&X[i4];
    __nv_bfloat16 h0, l0, h1, l1, h2, l2, h3, l3;
    bf16split(v.x, h0, l0); bf16split(v.y, h1, l1);
    bf16split(v.z, h2, l2); bf16split(v.w, h3, l3);
    uint2 ph, pl;
    ph.x = (uint32_t)__bfloat16_as_ushort(h0) | ((uint32_t)__bfloat16_as_ushort(h1) << 16);
    ph.y = (uint32_t)__bfloat16_as_ushort(h2) | ((uint32_t)__bfloat16_as_ushort(h3) << 16);
    pl.x = (uint32_t)__bfloat16_as_ushort(l0) | ((uint32_t)__bfloat16_as_ushort(l1) << 16);
    pl.y = (uint32_t)__bfloat16_as_ushort(l2) | ((uint32_t)__bfloat16_as_ushort(l3) << 16);
    *(uint2*)&g_xh[i4] = ph;
    *(uint2*)&g_xl[i4] = pl;
}

__global__ __launch_bounds__(256) void prep_w(
    const float* __restrict__ Wq, const float* __restrict__ Wk,
    const float* __restrict__ Wv, const float* __restrict__ Wo)
{
    const size_t i4 = ((size_t)blockIdx.x * 256 + threadIdx.x) * 4;   // < 524288
    const float* src;
    __nv_bfloat16 *dh, *dl;
    size_t off;
    if (i4 < 393216) {
        int seg = (int)(i4 / 131072);
        off = i4 % 131072;
        src = (seg == 0) ? Wq : (seg == 1) ? Wk : Wv;
        dh = g_wh + (size_t)seg * 131072;
        dl = g_wl + (size_t)seg * 131072;
    } else {
        off = i4 - 393216;
        src = Wo;
        dh = g_woh;
        dl = g_wol;
    }
    float4 v = *(const float4*)&src[off];
    __nv_bfloat16 h0, l0, h1, l1, h2, l2, h3, l3;
    bf16split(v.x, h0, l0); bf16split(v.y, h1, l1);
    bf16split(v.z, h2, l2); bf16split(v.w, h3, l3);
    uint2 ph, pl;
    ph.x = (uint32_t)__bfloat16_as_ushort(h0) | ((uint32_t)__bfloat16_as_ushort(h1) << 16);
    ph.y = (uint32_t)__bfloat16_as_ushort(h2) | ((uint32_t)__bfloat16_as_ushort(h3) << 16);
    pl.x = (uint32_t)__bfloat16_as_ushort(l0) | ((uint32_t)__bfloat16_as_ushort(l1) << 16);
    pl.y = (uint32_t)__bfloat16_as_ushort(l2) | ((uint32_t)__bfloat16_as_ushort(l3) << 16);
    *(uint2*)&dh[off] = ph;
    *(uint2*)&dl[off] = pl;
}

// ---------------------------------------------------------------------------
// HMMA GEMM, single fused K-sweep with hi/lo fragment reuse:
//   D = Ah*Bh + Al*Bh + Ah*Bl   (bf16 2-term split, lo*lo dropped)
// Block tile 128(J) x 128(tok), K slab 32. 8 warps = 4(m) x 2(n), warp 32x64.
// Slab staging via cp.async.cg (global->smem direct; removes the LDG->STS
// register round-trip, ~40% of the binding L1 traffic in R11's profile).
// B fragments in two bn-halves to keep natural reg demand ~110.
// Smem: 4 slabs (Ah, Al, Bh, Bl) 128 x 40(bf16) each = 40960 B static.
// MODE 0: A = W_cat [1536 x 256], B = X [32768 x 256] -> scatter to g_q/g_k/g_v
// MODE 1: A = Wo    [ 256 x 512], B = u [32768 x 512] -> out + bias
// ---------------------------------------------------------------------------
template <int MODE>
__global__ __launch_bounds__(256, 2) void gemm_mma(const float* __restrict__ bias,
                                                   float* __restrict__ outp)
{
    constexpr int KTOT = (MODE == 0) ? 256 : 512;
    constexpr int ST = 40;                       // bf16 per smem row (32 + 8 pad)
    constexpr int SLAB = 128 * ST;               // elems per slab

    __shared__ __align__(16) __nv_bfloat16 smem[4 * SLAB];   // 40960 B
    __nv_bfloat16* sAh = smem;
    __nv_bfloat16* sAl = smem + SLAB;
    __nv_bfloat16* sBh = smem + 2 * SLAB;
    __nv_bfloat16* sBl = smem + 3 * SLAB;

    const int tid = threadIdx.x;
    const int wid = tid >> 5;
    const int lane = tid & 31;
    const int wm = wid & 3;        // warp m (J) index: 4
    const int wn = wid >> 2;       // warp n (tok) index: 2
    const int J0 = blockIdx.x * 128;
    const int T0 = blockIdx.y * 128;

    float acc[2][8][4];
    #pragma unroll
    for (int am = 0; am < 2; am++)
        #pragma unroll
        for (int bn = 0; bn < 8; bn++)
            #pragma unroll
            for (int c = 0; c < 4; c++) acc[am][bn][c] = 0.0f;

    const int lrow = tid >> 1;       // 0..127
    const int lhalf = tid & 1;       // 32B half of the 64B slab row

    // store-side smem byte addresses (constant across slabs)
    const int so = lrow * ST + lhalf * 16;
    const uint32_t stAh = smem_u32(&sAh[so]);
    const uint32_t stAl = smem_u32(&sAl[so]);
    const uint32_t stBh = smem_u32(&sBh[so]);
    const uint32_t stBl = smem_u32(&sBl[so]);

    // fragment smem addresses (constant across slabs)
    const int ar = wm * 32 + (lane & 15);
    const int ac = (lane >> 4) << 3;
    const uint32_t aAh0 = smem_u32(&sAh[(ar)      * ST + ac]);
    const uint32_t aAh1 = smem_u32(&sAh[(ar + 16) * ST + ac]);
    const uint32_t aAl0 = smem_u32(&sAl[(ar)      * ST + ac]);
    const uint32_t aAl1 = smem_u32(&sAl[(ar + 16) * ST + ac]);
    const int br = wn * 64 + ((lane >> 4) << 3) + (lane & 7);
    const int bc = ((lane >> 3) & 1) << 3;
    const uint32_t aBh = smem_u32(&sBh[br * ST + bc]);
    const uint32_t aBl = smem_u32(&sBl[br * ST + bc]);

    for (int kk = 0; kk < KTOT; kk += 32) {
        // stage 4 slabs via cp.async: each thread = (row, 32B half) per slab
        {
            const __nv_bfloat16 *Ah, *Al, *Bh, *Bl;
            if (MODE == 0) { Ah = g_wh; Al = g_wl; Bh = g_xh; Bl = g_xl; }
            else           { Ah = g_woh; Al = g_wol; Bh = g_uh; Bl = g_ul; }
            const size_t ga = (size_t)(J0 + lrow) * KTOT + kk + lhalf * 16;
            const size_t gb = (size_t)(T0 + lrow) * KTOT + kk + lhalf * 16;
            cp_async16(stAh,      Ah + ga);
            cp_async16(stAh + 16, Ah + ga + 8);
            cp_async16(stAl,      Al + ga);
            cp_async16(stAl + 16, Al + ga + 8);
            cp_async16(stBh,      Bh + gb);
            cp_async16(stBh + 16, Bh + gb + 8);
            cp_async16(stBl,      Bl + gb);
            cp_async16(stBl + 16, Bl + gb + 8);
            CP_ASYNC_COMMIT();
            CP_ASYNC_WAIT0();
        }
        __syncthreads();
        #pragma unroll
        for (int ks = 0; ks < 2; ks++) {
            const int co = ks * 16 * 2;          // byte offset col shift: 16 bf16
            uint32_t ah[2][4], al[2][4];
            ldm_x4(ah[0][0], ah[0][1], ah[0][2], ah[0][3], aAh0 + co);
            ldm_x4(ah[1][0], ah[1][1], ah[1][2], ah[1][3], aAh1 + co);
            ldm_x4(al[0][0], al[0][1], al[0][2], al[0][3], aAl0 + co);
            ldm_x4(al[1][0], al[1][1], al[1][2], al[1][3], aAl1 + co);
            #pragma unroll
            for (int h2 = 0; h2 < 2; h2++) {     // bn half: fragments 4*h2 .. 4*h2+3
                uint32_t bb[4][2];
                #pragma unroll
                for (int j = 0; j < 2; j++)
                    ldm_x4(bb[2 * j][0], bb[2 * j][1], bb[2 * j + 1][0], bb[2 * j + 1][1],
                           aBh + (2 * h2 + j) * 16 * ST * 2 + co);
                #pragma unroll
                for (int am = 0; am < 2; am++)
                    #pragma unroll
                    for (int j4 = 0; j4 < 4; j4++)
                        mma_bf16(acc[am][4 * h2 + j4], ah[am], bb[j4]);
                #pragma unroll
                for (int am = 0; am < 2; am++)
                    #pragma unroll
                    for (int j4 = 0; j4 < 4; j4++)
                        mma_bf16(acc[am][4 * h2 + j4], al[am], bb[j4]);
                #pragma unroll
                for (int j = 0; j < 2; j++)
                    ldm_x4(bb[2 * j][0], bb[2 * j][1], bb[2 * j + 1][0], bb[2 * j + 1][1],
                           aBl + (2 * h2 + j) * 16 * ST * 2 + co);
                #pragma unroll
                for (int am = 0; am < 2; am++)
                    #pragma unroll
                    for (int j4 = 0; j4 < 4; j4++)
                        mma_bf16(acc[am][4 * h2 + j4], ah[am], bb[j4]);
            }
        }
        __syncthreads();
    }

    // Epilogue: two half-passes over tokens, staging transposed in smem.
    float* stage = (float*)smem;   // 64 x 132 fp32 = 33792 B (fits 40960)
    #pragma unroll 1
    for (int half = 0; half < 2; half++) {
        __syncthreads();
        if (wn == half) {
            #pragma unroll
            for (int am = 0; am < 2; am++)
                #pragma unroll
                for (int bn = 0; bn < 8; bn++)
                    #pragma unroll
                    for (int c = 0; c < 4; c++) {
                        const int ml = wm * 32 + am * 16 + (lane >> 2) + ((c >> 1) << 3);
                        const int nl = bn * 8 + (lane & 3) * 2 + (c & 1);
                        stage[nl * 132 + ml] = acc[am][bn][c];
                    }
        }
        __syncthreads();
        const int tok_l = tid >> 2;          // 0..63
        const int qg = tid & 3;              // 32-J group
        const float* srow = &stage[tok_l * 132 + qg * 32];
        const int m = T0 + half * 64 + tok_l;
        const int J = J0 + qg * 32;
        if (MODE == 0) {
            const int which = J >> 9;
            const int h = (J >> 6) & 7;
            const int d = J & 63;
            const int b = m >> 13;
            const int n = m & (NN - 1);
            float* dst = ((which == 0) ? g_q : (which == 1) ? g_k : g_v)
                         + (((size_t)(b * HH + h)) * NN + n) * DD + d;
            #pragma unroll
            for (int dd = 0; dd < 32; dd += 4)
                *(float4*)&dst[dd] = *(const float4*)&srow[dd];
        } else {
            float* dst = outp + (size_t)m * CC + J;
            #pragma unroll
            for (int dd = 0; dd < 32; dd += 4) {
                float4 v = *(const float4*)&srow[dd];
                float4 bv = *(const float4*)&bias[J + dd];
                v.x += bv.x; v.y += bv.y; v.z += bv.z; v.w += bv.w;
                *(float4*)&dst[dd] = v;
            }
        }
    }
}

// ---------------------------------------------------------------------------
// kv_dots: fused instance-norm(K,V) + RoPE(K), partial K^T V per chunk
// ---------------------------------------------------------------------------
__global__ __launch_bounds__(256) void kv_dots()
{
    __shared__ __align__(16) float Ks[16][64];
    __shared__ __align__(16) float Vs[16][64];

    const int chunk = blockIdx.x;
    const int bh = blockIdx.y;
    const int tid = threadIdx.x;
    const int w = tid >> 5;
    const int lane = tid & 31;
    const int jf = lane & 15;
    const float sgn = (lane < 16) ? -1.0f : 1.0f;
    const unsigned FULL = 0xffffffffu;

    const int tx = tid & 15;
    const int ty = tid >> 4;
    const int lt = tid >> 4;
    const int ld4 = (tid & 15) * 4;

    const size_t nbase = (size_t)bh * NN + (size_t)chunk * CHK;

    u64t acc[4][2];
    #pragma unroll
    for (int i = 0; i < 4; i++) { acc[i][0] = 0ull; acc[i][1] = 0ull; }

    for (int s = 0; s < CHK; s += 16) {
        *(float4*)&Ks[lt][ld4] = *(const float4*)&g_k[(nbase + s + lt) * DD + ld4];
        *(float4*)&Vs[lt][ld4] = *(const float4*)&g_v[(nbase + s + lt) * DD + ld4];
        __syncthreads();

        #pragma unroll
        for (int r = 0; r < 2; r++) {
            const int row = w * 2 + r;
            const int n = chunk * CHK + s + row;
            const float* T = &g_trig[(size_t)n * 64];
            const float cx = T[jf], sx = T[16 + jf], cy = T[32 + jf], sy = T[48 + jf];
            {
                float k0 = Ks[row][lane], k1 = Ks[row][32 + lane];
                float su = k0 + k1, ss = k0 * k0 + k1 * k1;
                #pragma unroll
                for (int o = 16; o > 0; o >>= 1) {
                    su += __shfl_xor_sync(FULL, su, o);
                    ss += __shfl_xor_sync(FULL, ss, o);
                }
                float mean = su * (1.0f / 64.0f);
                float var = ss * (1.0f / 64.0f) - mean * mean;
                float inv = rsqrtf(var + 1e-5f);
                k0 = (k0 - mean) * inv;
                k1 = (k1 - mean) * inv;
                float k0p = __shfl_xor_sync(FULL, k0, 16);
                float k1p = __shfl_xor_sync(FULL, k1, 16);
                Ks[row][lane]      = k0 * cx + sgn * k0p * sx;
                Ks[row][32 + lane] = k1 * cy + sgn * k1p * sy;
            }
            {
                float v0 = Vs[row][lane], v1 = Vs[row][32 + lane];
                float su = v0 + v1, ss = v0 * v0 + v1 * v1;
                #pragma unroll
                for (int o = 16; o > 0; o >>= 1) {
                    su += __shfl_xor_sync(FULL, su, o);
                    ss += __shfl_xor_sync(FULL, ss, o);
                }
                float mean = su * (1.0f / 64.0f);
                float var = ss * (1.0f / 64.0f) - mean * mean;
                float inv = rsqrtf(var + 1e-5f);
                Vs[row][lane]      = (v0 - mean) * inv;
                Vs[row][32 + lane] = (v1 - mean) * inv;
            }
        }
        __syncthreads();

        #pragma unroll
        for (int t = 0; t < 16; t++) {
            float4 av = *(const float4*)&Ks[t][ty * 4];
            float4 wv = *(const float4*)&Vs[t][tx * 4];
            u64t w2[2];
            w2[0] = ((const u64t*)&wv)[0];
            w2[1] = ((const u64t*)&wv)[1];
            float a[4] = {av.x, av.y, av.z, av.w};
            #pragma unroll
            for (int i = 0; i < 4; i++) {
                u64t ap = pack2(a[i]);
                acc[i][0] = ffma2(ap, w2[0], acc[i][0]);
                acc[i][1] = ffma2(ap, w2[1], acc[i][1]);
            }
        }
        __syncthreads();
    }

    float* P = &g_part[((size_t)chunk * (BB * HH) + bh) * (DD * DD)];
    #pragma unroll
    for (int i = 0; i < 4; i++) {
        float4 ov;
        unpack2(acc[i][0], ov.x, ov.y);
        unpack2(acc[i][1], ov.z, ov.w);
        *(float4*)&P[(ty * 4 + i) * DD + tx * 4] = ov;
    }
}

__global__ __launch_bounds__(256) void reduce_dots()
{
    const int i = blockIdx.x * 256 + threadIdx.x;
    float s = 0.0f;
    #pragma unroll
    for (int c = 0; c < NCHUNK; c++)
        s += g_part[(size_t)c * (BB * HH * DD * DD) + i];
    g_dots[i] = s * (1.0f / (float)NN);
}

// ---------------------------------------------------------------------------
// q_dots: u = rope(q) @ dots; outputs u as bf16 hi/lo at [m][h*64+d]
// ---------------------------------------------------------------------------
__global__ __launch_bounds__(256) void q_dots()
{
    __shared__ __align__(16) float Qs[64][65];
    __shared__ __align__(16) float Ds[64][64];

    const int bh = blockIdx.y;
    const int n0 = blockIdx.x * 64;
    const int tid = threadIdx.x;
    const int w = tid >> 5;
    const int lane = tid & 31;
    const int jf = lane & 15;
    const float sgn = (lane < 16) ? -1.0f : 1.0f;
    const unsigned FULL = 0xffffffffu;

    const int lt = tid >> 4;
    const int ld4 = (tid & 15) * 4;
    #pragma unroll
    for (int r = 0; r < 4; r++)
        *(float4*)&Ds[lt + 16 * r][ld4] =
            *(const float4*)&g_dots[(size_t)bh * (DD * DD) + (lt + 16 * r) * DD + ld4];

    #pragma unroll
    for (int r = 0; r < 8; r++) {
        const int trow = w * 8 + r;
        const int n = n0 + trow;
        const float* T = &g_trig[(size_t)n * 64];
        const float cx = T[jf], sx = T[16 + jf], cy = T[32 + jf], sy = T[48 + jf];
        const size_t base = ((size_t)bh * NN + n) * DD;
        float q0 = g_q[base + lane];
        float q1 = g_q[base + 32 + lane];
        float q0p = __shfl_xor_sync(FULL, q0, 16);
        float q1p = __shfl_xor_sync(FULL, q1, 16);
        Qs[trow][lane]      = q0 * cx + sgn * q0p * sx;
        Qs[trow][32 + lane] = q1 * cy + sgn * q1p * sy;
    }
    __syncthreads();

    const int tx = tid & 15;
    const int ty = tid >> 4;
    u64t acc[4][2];
    #pragma unroll
    for (int i = 0; i < 4; i++) { acc[i][0] = 0ull; acc[i][1] = 0ull; }

    #pragma unroll 4
    for (int k = 0; k < 64; k++) {
        float4 wv = *(const float4*)&Ds[k][tx * 4];
        u64t w2[2];
        w2[0] = ((const u64t*)&wv)[0];
        w2[1] = ((const u64t*)&wv)[1];
        #pragma unroll
        for (int i = 0; i < 4; i++) {
            u64t ap = pack2(Qs[ty * 4 + i][k]);
            acc[i][0] = ffma2(ap, w2[0], acc[i][0]);
            acc[i][1] = ffma2(ap, w2[1], acc[i][1]);
        }
    }

    const int b = bh >> 3;
    const int h = bh & 7;
    #pragma unroll
    for (int i = 0; i < 4; i++) {
        float4 ov;
        unpack2(acc[i][0], ov.x, ov.y);
        unpack2(acc[i][1], ov.z, ov.w);
        const size_t m = (size_t)b * NN + (n0 + ty * 4 + i);
        const size_t off = m * HD + h * DD + tx * 4;
        __nv_bfloat16 h0, l0, h1, l1, h2, l2, h3, l3;
        bf16split(ov.x, h0, l0); bf16split(ov.y, h1, l1);
        bf16split(ov.z, h2, l2); bf16split(ov.w, h3, l3);
        uint2 ph, pl;
        ph.x = (uint32_t)__bfloat16_as_ushort(h0) | ((uint32_t)__bfloat16_as_ushort(h1) << 16);
        ph.y = (uint32_t)__bfloat16_as_ushort(h2) | ((uint32_t)__bfloat16_as_ushort(h3) << 16);
        pl.x = (uint32_t)__bfloat16_as_ushort(l0) | ((uint32_t)__bfloat16_as_ushort(l1) << 16);
        pl.y = (uint32_t)__bfloat16_as_ushort(l2) | ((uint32_t)__bfloat16_as_ushort(l3) << 16);
        *(uint2*)&g_uh[off] = ph;
        *(uint2*)&g_ul[off] = pl;
    }
}

// ---------------------------------------------------------------------------
extern "C" void kernel_launch(void* const* d_in, const int* in_sizes, int n_in,
                              void* d_out, int out_size)
{
    const float* ux  = (const float*)d_in[0];
    const float* pos = (const float*)d_in[1];
    const float* Wq  = (const float*)d_in[2];
    const float* Wk  = (const float*)d_in[3];
    const float* Wv  = (const float*)d_in[4];
    const float* Wo  = (const float*)d_in[5];
    const float* bo  = (const float*)d_in[6];
    float* out = (float*)d_out;

    trig_init<<<(NN * 16) / 256, 256>>>(pos);
    prep_x<<<(32768 * 256) / (256 * 4), 256>>>(ux);
    prep_w<<<524288 / (256 * 4), 256>>>(Wq, Wk, Wv, Wo);
    gemm_mma<0><<<dim3(12, 256), 256>>>(nullptr, nullptr);
    kv_dots<<<dim3(NCHUNK, BB * HH), 256>>>();
    reduce_dots<<<(BB * HH * DD * DD) / 256, 256>>>();
    q_dots<<<dim3(NN / 64, BB * HH), 256>>>();
    gemm_mma<1><<<dim3(2, 256), 256>>>(bo, out);
}

// round 14
// speedup vs baseline: 1.2695x; 1.0132x over previous
#include <cuda_runtime.h>
#include <cuda_bf16.h>
#include <math.h>
#include <stdint.h>

#define BB 4
#define NN 8192
#define CC 256
#define HH 8
#define DD 64
#define HD 512
#define NCHUNK 16
#define CHK (NN / NCHUNK)   // 512

typedef unsigned long long u64t;

// ---------------------------------------------------------------------------
// Scratch (__device__ globals; allocation-free rule)
// ---------------------------------------------------------------------------
__device__ float g_q[BB * HH * NN * DD];            // [bh][n][d] fp32
__device__ float g_k[BB * HH * NN * DD];
__device__ float g_v[BB * HH * NN * DD];
__device__ float g_part[NCHUNK * BB * HH * DD * DD];
__device__ float g_dots[BB * HH * DD * DD];
__device__ float g_trig[NN * 64];                   // per n: cx[16] sx[16] cy[16] sy[16]

__device__ __nv_bfloat16 g_xh[32768 * 256];         // X split
__device__ __nv_bfloat16 g_xl[32768 * 256];
__device__ __nv_bfloat16 g_wh[1536 * 256];          // [Wq;Wk;Wv] split
__device__ __nv_bfloat16 g_wl[1536 * 256];
__device__ __nv_bfloat16 g_woh[256 * 512];          // Wo split
__device__ __nv_bfloat16 g_wol[256 * 512];
__device__ __nv_bfloat16 g_uh[32768 * 512];         // u split, [m][h*64+d]
__device__ __nv_bfloat16 g_ul[32768 * 512];

// ---------------------------------------------------------------------------
// helpers
// ---------------------------------------------------------------------------
__device__ __forceinline__ uint32_t smem_u32(const void* p) {
    uint32_t a;
    asm("{ .reg .u64 t; cvta.to.shared.u64 t, %1; cvt.u32.u64 %0, t; }" : "=r"(a) : "l"(p));
    return a;
}
__device__ __forceinline__ void ldm_x4(uint32_t& r0, uint32_t& r1, uint32_t& r2, uint32_t& r3,
                                       uint32_t addr) {
    asm volatile("ldmatrix.sync.aligned.m8n8.x4.shared.b16 {%0,%1,%2,%3}, [%4];"
                 : "=r"(r0), "=r"(r1), "=r"(r2), "=r"(r3) : "r"(addr));
}
__device__ __forceinline__ void mma_bf16(float* d, const uint32_t* a, const uint32_t* b) {
    asm volatile(
        "mma.sync.aligned.m16n8k16.row.col.f32.bf16.bf16.f32 "
        "{%0,%1,%2,%3}, {%4,%5,%6,%7}, {%8,%9}, {%0,%1,%2,%3};"
        : "+f"(d[0]), "+f"(d[1]), "+f"(d[2]), "+f"(d[3])
        : "r"(a[0]), "r"(a[1]), "r"(a[2]), "r"(a[3]), "r"(b[0]), "r"(b[1]));
}
// cp.async: global -> smem direct, bypassing the register file / L1 writeback.
__device__ __forceinline__ void cp_async16(uint32_t smem_addr, const void* gptr) {
    asm volatile("cp.async.cg.shared.global [%0], [%1], 16;"
                 :: "r"(smem_addr), "l"(gptr) : "memory");
}
#define CP_ASYNC_COMMIT() asm volatile("cp.async.commit_group;" ::: "memory")
#define CP_ASYNC_WAIT0()  asm volatile("cp.async.wait_group 0;" ::: "memory")
#define CP_ASYNC_WAIT1()  asm volatile("cp.async.wait_group 1;" ::: "memory")

// ---- packed f32x2 helpers (SIMT kernels) ----------------------------------
__device__ __forceinline__ u64t ffma2(u64t a, u64t b, u64t c) {
    u64t d;
    asm("fma.rn.f32x2 %0, %1, %2, %3;" : "=l"(d) : "l"(a), "l"(b), "l"(c));
    return d;
}
__device__ __forceinline__ u64t pack2(float x) {
    u64t d;
    asm("mov.b64 %0, {%1, %1};" : "=l"(d) : "r"(__float_as_uint(x)));
    return d;
}
__device__ __forceinline__ void unpack2(u64t v, float& lo, float& hi) {
    unsigned a, b;
    asm("mov.b64 {%0, %1}, %2;" : "=r"(a), "=r"(b) : "l"(v));
    lo = __uint_as_float(a);
    hi = __uint_as_float(b);
}
__device__ __forceinline__ void bf16split(float x, __nv_bfloat16& h, __nv_bfloat16& l) {
    h = __float2bfloat16_rn(x);
    l = __float2bfloat16_rn(x - __bfloat162float(h));
}

// ---------------------------------------------------------------------------
// trig table
// ---------------------------------------------------------------------------
__global__ __launch_bounds__(256) void trig_init(const float* __restrict__ pos)
{
    const int idx = blockIdx.x * 256 + threadIdx.x;
    const int n = idx >> 4;
    const int j = idx & 15;
    const float invf = exp2f(-(float)j * (13.2877123795494f / 16.0f));
    const float px = pos[n * 2 + 0];
    const float py = pos[n * 2 + 1];
    float cx, sx, cy, sy;
    sincosf(px * 64.0f * invf, &sx, &cx);
    sincosf(py * 64.0f * invf, &sy, &cy);
    float* T = &g_trig[(size_t)n * 64];
    T[j] = cx; T[16 + j] = sx; T[32 + j] = cy; T[48 + j] = sy;
}

// ---------------------------------------------------------------------------
// prep: split X and weights into bf16 hi/lo
// ---------------------------------------------------------------------------
__global__ __launch_bounds__(256) void prep_x(const float* __restrict__ X)
{
    const size_t i4 = ((size_t)blockIdx.x * 256 + threadIdx.x) * 4;
    float4 v = *(const float4*)&X[i4];
    __nv_bfloat16 h0, l0, h1, l1, h2, l2, h3, l3;
    bf16split(v.x, h0, l0); bf16split(v.y, h1, l1);
    bf16split(v.z, h2, l2); bf16split(v.w, h3, l3);
    uint2 ph, pl;
    ph.x = (uint32_t)__bfloat16_as_ushort(h0) | ((uint32_t)__bfloat16_as_ushort(h1) << 16);
    ph.y = (uint32_t)__bfloat16_as_ushort(h2) | ((uint32_t)__bfloat16_as_ushort(h3) << 16);
    pl.x = (uint32_t)__bfloat16_as_ushort(l0) | ((uint32_t)__bfloat16_as_ushort(l1) << 16);
    pl.y = (uint32_t)__bfloat16_as_ushort(l2) | ((uint32_t)__bfloat16_as_ushort(l3) << 16);
    *(uint2*)&g_xh[i4] = ph;
    *(uint2*)&g_xl[i4] = pl;
}

__global__ __launch_bounds__(256) void prep_w(
    const float* __restrict__ Wq, const float* __restrict__ Wk,
    const float* __restrict__ Wv, const float* __restrict__ Wo)
{
    const size_t i4 = ((size_t)blockIdx.x * 256 + threadIdx.x) * 4;   // < 524288
    const float* src;
    __nv_bfloat16 *dh, *dl;
    size_t off;
    if (i4 < 393216) {
        int seg = (int)(i4 / 131072);
        off = i4 % 131072;
        src = (seg == 0) ? Wq : (seg == 1) ? Wk : Wv;
        dh = g_wh + (size_t)seg * 131072;
        dl = g_wl + (size_t)seg * 131072;
    } else {
        off = i4 - 393216;
        src = Wo;
        dh = g_woh;
        dl = g_wol;
    }
    float4 v = *(const float4*)&src[off];
    __nv_bfloat16 h0, l0, h1, l1, h2, l2, h3, l3;
    bf16split(v.x, h0, l0); bf16split(v.y, h1, l1);
    bf16split(v.z, h2, l2); bf16split(v.w, h3, l3);
    uint2 ph, pl;
    ph.x = (uint32_t)__bfloat16_as_ushort(h0) | ((uint32_t)__bfloat16_as_ushort(h1) << 16);
    ph.y = (uint32_t)__bfloat16_as_ushort(h2) | ((uint32_t)__bfloat16_as_ushort(h3) << 16);
    pl.x = (uint32_t)__bfloat16_as_ushort(l0) | ((uint32_t)__bfloat16_as_ushort(l1) << 16);
    pl.y = (uint32_t)__bfloat16_as_ushort(l2) | ((uint32_t)__bfloat16_as_ushort(l3) << 16);
    *(uint2*)&dh[off] = ph;
    *(uint2*)&dl[off] = pl;
}

// ---------------------------------------------------------------------------
// HMMA GEMM, double-buffered cp.async pipeline (K stage = 16):
//   D = Ah*Bh + Al*Bh + Ah*Bl   (bf16 2-term split, lo*lo dropped)
// Block tile 128(J) x 128(tok). 8 warps = 4(m) x 2(n), warp 32x64.
// Combined slab rows: [hi 32B | lo 32B | 16B pad] (ST=40, 80B stride,
// ldmatrix conflict-free). 2 buffers x (A slab + B slab) = 40960 B static.
// Pipeline: prefetch stage s+1 via cp.async while computing stage s.
// MODE 0: A = W_cat [1536 x 256], B = X [32768 x 256] -> scatter to g_q/g_k/g_v
// MODE 1: A = Wo    [ 256 x 512], B = u [32768 x 512] -> out + bias
// ---------------------------------------------------------------------------
template <int MODE>
__global__ __launch_bounds__(256, 2) void gemm_mma(const float* __restrict__ bias,
                                                   float* __restrict__ outp)
{
    constexpr int KTOT = (MODE == 0) ? 256 : 512;
    constexpr int NSTAGE = KTOT / 16;
    constexpr int ST = 40;                 // bf16 per combined row (16 hi + 16 lo + 8 pad)
    constexpr int SLAB = 128 * ST;         // elems per slab (A or B): 5120 (10240 B)
    constexpr int BUFB = 4 * SLAB;         // BYTES per buffer (A+B): 20480

    __shared__ __align__(16) __nv_bfloat16 smem[4 * SLAB];   // 40960 B (2 buffers)

    const int tid = threadIdx.x;
    const int wid = tid >> 5;
    const int lane = tid & 31;
    const int wm = wid & 3;        // warp m (J) index: 4
    const int wn = wid >> 2;       // warp n (tok) index: 2
    const int J0 = blockIdx.x * 128;
    const int T0 = blockIdx.y * 128;

    float acc[2][8][4];
    #pragma unroll
    for (int am = 0; am < 2; am++)
        #pragma unroll
        for (int bn = 0; bn < 8; bn++)
            #pragma unroll
            for (int c = 0; c < 4; c++) acc[am][bn][c] = 0.0f;

    const int lrow = tid >> 1;       // 0..127
    const int lhalf = tid & 1;       // 16B half of the 32B hi (or lo) row chunk

    // global source pointers
    const __nv_bfloat16 *Ah, *Al, *Bh, *Bl;
    if (MODE == 0) { Ah = g_wh; Al = g_wl; Bh = g_xh; Bl = g_xl; }
    else           { Ah = g_woh; Al = g_wol; Bh = g_uh; Bl = g_ul; }
    const __nv_bfloat16* gA_h = Ah + (size_t)(J0 + lrow) * KTOT + lhalf * 8;
    const __nv_bfloat16* gA_l = Al + (size_t)(J0 + lrow) * KTOT + lhalf * 8;
    const __nv_bfloat16* gB_h = Bh + (size_t)(T0 + lrow) * KTOT + lhalf * 8;
    const __nv_bfloat16* gB_l = Bl + (size_t)(T0 + lrow) * KTOT + lhalf * 8;

    // store-side smem byte addresses (buffer 0)
    const uint32_t smb = smem_u32(smem);
    const uint32_t stA = smb + (uint32_t)(lrow * ST * 2) + lhalf * 16;      // hi chunk
    const uint32_t stB = stA + (uint32_t)(SLAB * 2);                         // B slab
    // lo chunk at +32 bytes within the row

    // fragment smem byte addresses (buffer 0)
    const int ar = wm * 32 + (lane & 15);
    const int ac = (lane >> 4) << 3;
    const uint32_t aAh0 = smb + (uint32_t)((ar * ST + ac) * 2);
    const uint32_t aAh1 = smb + (uint32_t)(((ar + 16) * ST + ac) * 2);
    const uint32_t aAl0 = aAh0 + 32;
    const uint32_t aAl1 = aAh1 + 32;
    const int br = wn * 64 + ((lane >> 4) << 3) + (lane & 7);
    const int bc = ((lane >> 3) & 1) << 3;
    const uint32_t aBh = smb + (uint32_t)(SLAB * 2) + (uint32_t)((br * ST + bc) * 2);
    const uint32_t aBl = aBh + 32;

    // prologue: stage 0 into buffer 0
    {
        cp_async16(stA,      gA_h);
        cp_async16(stA + 32, gA_l);
        cp_async16(stB,      gB_h);
        cp_async16(stB + 32, gB_l);
        CP_ASYNC_COMMIT();
    }

    for (int s = 0; s < NSTAGE; s++) {
        if (s + 1 < NSTAGE) {
            const uint32_t bo = ((s + 1) & 1) * BUFB;
            const int kn = (s + 1) * 16;
            cp_async16(stA + bo,      gA_h + kn);
            cp_async16(stA + bo + 32, gA_l + kn);
            cp_async16(stB + bo,      gB_h + kn);
            cp_async16(stB + bo + 32, gB_l + kn);
            CP_ASYNC_COMMIT();
            CP_ASYNC_WAIT1();          // current stage's group done; prefetch in flight
        } else {
            CP_ASYNC_WAIT0();
        }
        __syncthreads();

        const uint32_t bo = (s & 1) * BUFB;
        uint32_t ah[2][4], al[2][4];
        ldm_x4(ah[0][0], ah[0][1], ah[0][2], ah[0][3], aAh0 + bo);
        ldm_x4(ah[1][0], ah[1][1], ah[1][2], ah[1][3], aAh1 + bo);
        ldm_x4(al[0][0], al[0][1], al[0][2], al[0][3], aAl0 + bo);
        ldm_x4(al[1][0], al[1][1], al[1][2], al[1][3], aAl1 + bo);
        #pragma unroll
        for (int h2 = 0; h2 < 2; h2++) {     // bn half: fragments 4*h2 .. 4*h2+3
            uint32_t bb[4][2];
            #pragma unroll
            for (int j = 0; j < 2; j++)
                ldm_x4(bb[2 * j][0], bb[2 * j][1], bb[2 * j + 1][0], bb[2 * j + 1][1],
                       aBh + bo + (2 * h2 + j) * 16 * ST * 2);
            #pragma unroll
            for (int am = 0; am < 2; am++)
                #pragma unroll
                for (int j4 = 0; j4 < 4; j4++)
                    mma_bf16(acc[am][4 * h2 + j4], ah[am], bb[j4]);
            #pragma unroll
            for (int am = 0; am < 2; am++)
                #pragma unroll
                for (int j4 = 0; j4 < 4; j4++)
                    mma_bf16(acc[am][4 * h2 + j4], al[am], bb[j4]);
            #pragma unroll
            for (int j = 0; j < 2; j++)
                ldm_x4(bb[2 * j][0], bb[2 * j][1], bb[2 * j + 1][0], bb[2 * j + 1][1],
                       aBl + bo + (2 * h2 + j) * 16 * ST * 2);
            #pragma unroll
            for (int am = 0; am < 2; am++)
                #pragma unroll
                for (int j4 = 0; j4 < 4; j4++)
                    mma_bf16(acc[am][4 * h2 + j4], ah[am], bb[j4]);
        }
        __syncthreads();
    }

    // Epilogue: two half-passes over tokens, staging transposed in smem.
    float* stage = (float*)smem;   // 64 x 132 fp32 = 33792 B (fits 40960)
    #pragma unroll 1
    for (int half = 0; half < 2; half++) {
        __syncthreads();
        if (wn == half) {
            #pragma unroll
            for (int am = 0; am < 2; am++)
                #pragma unroll
                for (int bn = 0; bn < 8; bn++)
                    #pragma unroll
                    for (int c = 0; c < 4; c++) {
                        const int ml = wm * 32 + am * 16 + (lane >> 2) + ((c >> 1) << 3);
                        const int nl = bn * 8 + (lane & 3) * 2 + (c & 1);
                        stage[nl * 132 + ml] = acc[am][bn][c];
                    }
        }
        __syncthreads();
        const int tok_l = tid >> 2;          // 0..63
        const int qg = tid & 3;              // 32-J group
        const float* srow = &stage[tok_l * 132 + qg * 32];
        const int m = T0 + half * 64 + tok_l;
        const int J = J0 + qg * 32;
        if (MODE == 0) {
            const int which = J >> 9;
            const int h = (J >> 6) & 7;
            const int d = J & 63;
            const int b = m >> 13;
            const int n = m & (NN - 1);
            float* dst = ((which == 0) ? g_q : (which == 1) ? g_k : g_v)
                         + (((size_t)(b * HH + h)) * NN + n) * DD + d;
            #pragma unroll
            for (int dd = 0; dd < 32; dd += 4)
                *(float4*)&dst[dd] = *(const float4*)&srow[dd];
        } else {
            float* dst = outp + (size_t)m * CC + J;
            #pragma unroll
            for (int dd = 0; dd < 32; dd += 4) {
                float4 v = *(const float4*)&srow[dd];
                float4 bv = *(const float4*)&bias[J + dd];
                v.x += bv.x; v.y += bv.y; v.z += bv.z; v.w += bv.w;
                *(float4*)&dst[dd] = v;
            }
        }
    }
}

// ---------------------------------------------------------------------------
// kv_dots: fused instance-norm(K,V) + RoPE(K), partial K^T V per chunk
// ---------------------------------------------------------------------------
__global__ __launch_bounds__(256) void kv_dots()
{
    __shared__ __align__(16) float Ks[16][64];
    __shared__ __align__(16) float Vs[16][64];

    const int chunk = blockIdx.x;
    const int bh = blockIdx.y;
    const int tid = threadIdx.x;
    const int w = tid >> 5;
    const int lane = tid & 31;
    const int jf = lane & 15;
    const float sgn = (lane < 16) ? -1.0f : 1.0f;
    const unsigned FULL = 0xffffffffu;

    const int tx = tid & 15;
    const int ty = tid >> 4;
    const int lt = tid >> 4;
    const int ld4 = (tid & 15) * 4;

    const size_t nbase = (size_t)bh * NN + (size_t)chunk * CHK;

    u64t acc[4][2];
    #pragma unroll
    for (int i = 0; i < 4; i++) { acc[i][0] = 0ull; acc[i][1] = 0ull; }

    for (int s = 0; s < CHK; s += 16) {
        *(float4*)&Ks[lt][ld4] = *(const float4*)&g_k[(nbase + s + lt) * DD + ld4];
        *(float4*)&Vs[lt][ld4] = *(const float4*)&g_v[(nbase + s + lt) * DD + ld4];
        __syncthreads();

        #pragma unroll
        for (int r = 0; r < 2; r++) {
            const int row = w * 2 + r;
            const int n = chunk * CHK + s + row;
            const float* T = &g_trig[(size_t)n * 64];
            const float cx = T[jf], sx = T[16 + jf], cy = T[32 + jf], sy = T[48 + jf];
            {
                float k0 = Ks[row][lane], k1 = Ks[row][32 + lane];
                float su = k0 + k1, ss = k0 * k0 + k1 * k1;
                #pragma unroll
                for (int o = 16; o > 0; o >>= 1) {
                    su += __shfl_xor_sync(FULL, su, o);
                    ss += __shfl_xor_sync(FULL, ss, o);
                }
                float mean = su * (1.0f / 64.0f);
                float var = ss * (1.0f / 64.0f) - mean * mean;
                float inv = rsqrtf(var + 1e-5f);
                k0 = (k0 - mean) * inv;
                k1 = (k1 - mean) * inv;
                float k0p = __shfl_xor_sync(FULL, k0, 16);
                float k1p = __shfl_xor_sync(FULL, k1, 16);
                Ks[row][lane]      = k0 * cx + sgn * k0p * sx;
                Ks[row][32 + lane] = k1 * cy + sgn * k1p * sy;
            }
            {
                float v0 = Vs[row][lane], v1 = Vs[row][32 + lane];
                float su = v0 + v1, ss = v0 * v0 + v1 * v1;
                #pragma unroll
                for (int o = 16; o > 0; o >>= 1) {
                    su += __shfl_xor_sync(FULL, su, o);
                    ss += __shfl_xor_sync(FULL, ss, o);
                }
                float mean = su * (1.0f / 64.0f);
                float var = ss * (1.0f / 64.0f) - mean * mean;
                float inv = rsqrtf(var + 1e-5f);
                Vs[row][lane]      = (v0 - mean) * inv;
                Vs[row][32 + lane] = (v1 - mean) * inv;
            }
        }
        __syncthreads();

        #pragma unroll
        for (int t = 0; t < 16; t++) {
            float4 av = *(const float4*)&Ks[t][ty * 4];
            float4 wv = *(const float4*)&Vs[t][tx * 4];
            u64t w2[2];
            w2[0] = ((const u64t*)&wv)[0];
            w2[1] = ((const u64t*)&wv)[1];
            float a[4] = {av.x, av.y, av.z, av.w};
            #pragma unroll
            for (int i = 0; i < 4; i++) {
                u64t ap = pack2(a[i]);
                acc[i][0] = ffma2(ap, w2[0], acc[i][0]);
                acc[i][1] = ffma2(ap, w2[1], acc[i][1]);
            }
        }
        __syncthreads();
    }

    float* P = &g_part[((size_t)chunk * (BB * HH) + bh) * (DD * DD)];
    #pragma unroll
    for (int i = 0; i < 4; i++) {
        float4 ov;
        unpack2(acc[i][0], ov.x, ov.y);
        unpack2(acc[i][1], ov.z, ov.w);
        *(float4*)&P[(ty * 4 + i) * DD + tx * 4] = ov;
    }
}

__global__ __launch_bounds__(256) void reduce_dots()
{
    const int i = blockIdx.x * 256 + threadIdx.x;
    float s = 0.0f;
    #pragma unroll
    for (int c = 0; c < NCHUNK; c++)
        s += g_part[(size_t)c * (BB * HH * DD * DD) + i];
    g_dots[i] = s * (1.0f / (float)NN);
}

// ---------------------------------------------------------------------------
// q_dots: u = rope(q) @ dots; outputs u as bf16 hi/lo at [m][h*64+d]
// ---------------------------------------------------------------------------
__global__ __launch_bounds__(256) void q_dots()
{
    __shared__ __align__(16) float Qs[64][65];
    __shared__ __align__(16) float Ds[64][64];

    const int bh = blockIdx.y;
    const int n0 = blockIdx.x * 64;
    const int tid = threadIdx.x;
    const int w = tid >> 5;
    const int lane = tid & 31;
    const int jf = lane & 15;
    const float sgn = (lane < 16) ? -1.0f : 1.0f;
    const unsigned FULL = 0xffffffffu;

    const int lt = tid >> 4;
    const int ld4 = (tid & 15) * 4;
    #pragma unroll
    for (int r = 0; r < 4; r++)
        *(float4*)&Ds[lt + 16 * r][ld4] =
            *(const float4*)&g_dots[(size_t)bh * (DD * DD) + (lt + 16 * r) * DD + ld4];

    #pragma unroll
    for (int r = 0; r < 8; r++) {
        const int trow = w * 8 + r;
        const int n = n0 + trow;
        const float* T = &g_trig[(size_t)n * 64];
        const float cx = T[jf], sx = T[16 + jf], cy = T[32 + jf], sy = T[48 + jf];
        const size_t base = ((size_t)bh * NN + n) * DD;
        float q0 = g_q[base + lane];
        float q1 = g_q[base + 32 + lane];
        float q0p = __shfl_xor_sync(FULL, q0, 16);
        float q1p = __shfl_xor_sync(FULL, q1, 16);
        Qs[trow][lane]      = q0 * cx + sgn * q0p * sx;
        Qs[trow][32 + lane] = q1 * cy + sgn * q1p * sy;
    }
    __syncthreads();

    const int tx = tid & 15;
    const int ty = tid >> 4;
    u64t acc[4][2];
    #pragma unroll
    for (int i = 0; i < 4; i++) { acc[i][0] = 0ull; acc[i][1] = 0ull; }

    #pragma unroll 4
    for (int k = 0; k < 64; k++) {
        float4 wv = *(const float4*)&Ds[k][tx * 4];
        u64t w2[2];
        w2[0] = ((const u64t*)&wv)[0];
        w2[1] = ((const u64t*)&wv)[1];
        #pragma unroll
        for (int i = 0; i < 4; i++) {
            u64t ap = pack2(Qs[ty * 4 + i][k]);
            acc[i][0] = ffma2(ap, w2[0], acc[i][0]);
            acc[i][1] = ffma2(ap, w2[1], acc[i][1]);
        }
    }

    const int b = bh >> 3;
    const int h = bh & 7;
    #pragma unroll
    for (int i = 0; i < 4; i++) {
        float4 ov;
        unpack2(acc[i][0], ov.x, ov.y);
        unpack2(acc[i][1], ov.z, ov.w);
        const size_t m = (size_t)b * NN + (n0 + ty * 4 + i);
        const size_t off = m * HD + h * DD + tx * 4;
        __nv_bfloat16 h0, l0, h1, l1, h2, l2, h3, l3;
        bf16split(ov.x, h0, l0); bf16split(ov.y, h1, l1);
        bf16split(ov.z, h2, l2); bf16split(ov.w, h3, l3);
        uint2 ph, pl;
        ph.x = (uint32_t)__bfloat16_as_ushort(h0) | ((uint32_t)__bfloat16_as_ushort(h1) << 16);
        ph.y = (uint32_t)__bfloat16_as_ushort(h2) | ((uint32_t)__bfloat16_as_ushort(h3) << 16);
        pl.x = (uint32_t)__bfloat16_as_ushort(l0) | ((uint32_t)__bfloat16_as_ushort(l1) << 16);
        pl.y = (uint32_t)__bfloat16_as_ushort(l2) | ((uint32_t)__bfloat16_as_ushort(l3) << 16);
        *(uint2*)&g_uh[off] = ph;
        *(uint2*)&g_ul[off] = pl;
    }
}

// ---------------------------------------------------------------------------
extern "C" void kernel_launch(void* const* d_in, const int* in_sizes, int n_in,
                              void* d_out, int out_size)
{
    const float* ux  = (const float*)d_in[0];
    const float* pos = (const float*)d_in[1];
    const float* Wq  = (const float*)d_in[2];
    const float* Wk  = (const float*)d_in[3];
    const float* Wv  = (const float*)d_in[4];
    const float* Wo  = (const float*)d_in[5];
    const float* bo  = (const float*)d_in[6];
    float* out = (float*)d_out;

    trig_init<<<(NN * 16) / 256, 256>>>(pos);
    prep_x<<<(32768 * 256) / (256 * 4), 256>>>(ux);
    prep_w<<<524288 / (256 * 4), 256>>>(Wq, Wk, Wv, Wo);
    gemm_mma<0><<<dim3(12, 256), 256>>>(nullptr, nullptr);
    kv_dots<<<dim3(NCHUNK, BB * HH), 256>>>();
    reduce_dots<<<(BB * HH * DD * DD) / 256, 256>>>();
    q_dots<<<dim3(NN / 64, BB * HH), 256>>>();
    gemm_mma<1><<<dim3(2, 256), 256>>>(bo, out);
}